// round 2
// baseline (speedup 1.0000x reference)
#include <cuda_runtime.h>
#include <cstdint>
#include <math.h>

// Problem constants (fixed shapes for this problem instance)
#define Bv 4
#define Lv 2048
#define Kv 32
#define FD 416   // 16 pos + 25*16 rbf
#define CD 128

// Scratch (allocation-free rule: __device__ globals)
__device__ float g_atoms[Bv*Lv*5*3];   // [b][l][atom 0..4][xyz], atoms = N,Ca,C,O,Cb
__device__ float g_ca[Bv*Lv*3];        // Ca only, contiguous for distance kernel
__device__ int   g_eidx[Bv*Lv*Kv];
__device__ float g_dn[Bv*Lv*Kv];       // D_neighbors (= selected D_adjust)

__constant__ int c_PA[24] = {0,2,3,4,1,1,1,1,0,0,0,4,4,3,0,2,3,4,2,3,4,2,3,2};
__constant__ int c_PB[24] = {0,2,3,4,0,2,3,4,2,3,4,2,3,2,1,1,1,1,0,0,0,4,4,3};

__device__ __forceinline__ unsigned long long umin64(unsigned long long a, unsigned long long b) {
    return a < b ? a : b;
}
__device__ __forceinline__ unsigned long long pk2(float lo, float hi) {
    unsigned long long r;
    asm("mov.b64 %0, {%1, %2};" : "=l"(r) : "f"(lo), "f"(hi));
    return r;
}
__device__ __forceinline__ void upk2(unsigned long long v, float& lo, float& hi) {
    asm("mov.b64 {%0, %1}, %2;" : "=f"(lo), "=f"(hi) : "l"(v));
}
__device__ __forceinline__ void ffma2(unsigned long long& d, unsigned long long a, unsigned long long b) {
    asm("fma.rn.f32x2 %0, %1, %2, %0;" : "+l"(d) : "l"(a), "l"(b));
}

// ---------------------------------------------------------------------------
// Kernel 1: build atom table (N, Ca, C, O, Cb)
// ---------------------------------------------------------------------------
__global__ void k1_atoms(const float* __restrict__ X) {
    int i = blockIdx.x * blockDim.x + threadIdx.x;
    if (i >= Bv*Lv) return;
    const float* x = X + (size_t)i * 12;
    float Nx=x[0],Ny=x[1],Nz=x[2];
    float Ax=x[3],Ay=x[4],Az=x[5];
    float Cx=x[6],Cy=x[7],Cz=x[8];
    float Ox=x[9],Oy=x[10],Oz=x[11];
    float bx=Ax-Nx, by=Ay-Ny, bz=Az-Nz;
    float cx=Cx-Ax, cy=Cy-Ay, cz=Cz-Az;
    float ax=by*cz-bz*cy, ay=bz*cx-bx*cz, az=bx*cy-by*cx;
    float Cbx = -0.58273431f*ax + 0.56802827f*bx - 0.54067466f*cx + Ax;
    float Cby = -0.58273431f*ay + 0.56802827f*by - 0.54067466f*cy + Ay;
    float Cbz = -0.58273431f*az + 0.56802827f*bz - 0.54067466f*cz + Az;
    float* p = g_atoms + (size_t)i * 15;
    p[0]=Nx; p[1]=Ny; p[2]=Nz;
    p[3]=Ax; p[4]=Ay; p[5]=Az;
    p[6]=Cx; p[7]=Cy; p[8]=Cz;
    p[9]=Ox; p[10]=Oy; p[11]=Oz;
    p[12]=Cbx; p[13]=Cby; p[14]=Cbz;
    g_ca[i*3+0]=Ax; g_ca[i*3+1]=Ay; g_ca[i*3+2]=Az;
}

// ---------------------------------------------------------------------------
// Kernel 2: top-K per row, one WARP per row (8 rows / 256-thread block).
// Lane l owns columns j with (j & 31) == l, so invalidate+rescan is lane-local
// and the selection loop needs NO barriers (shfl-only reduction).
// Key = (float_bits(D_adjust) << 32) | j reproduces jax.lax.top_k ordering.
// ---------------------------------------------------------------------------
__global__ void k2_topk(const float* __restrict__ mask) {
    extern __shared__ char smem_raw[];
    float* ca_s = (float*)smem_raw;          // Lv*3 floats (24KB)
    float* dist = ca_s + Lv*3;               // 8 * Lv floats (64KB)

    int tid  = threadIdx.x;
    int warp = tid >> 5, lane = tid & 31;
    int row0 = blockIdx.x * 8;               // 8 rows per block, same batch b
    int b    = row0 >> 11;

    const float* cab = g_ca + (size_t)b * Lv * 3;
    for (int i = tid; i < Lv*3; i += 256) ca_s[i] = cab[i];
    __syncthreads();

    int row = row0 + warp;
    int li  = row & (Lv-1);
    float xi = ca_s[li*3+0], yi = ca_s[li*3+1], zi = ca_s[li*3+2];
    float mi = mask[row];
    const float* mb = mask + (size_t)b * Lv;
    float* dw = dist + warp * Lv;

    // pass 1: distances + row max
    float lmax = 0.0f;
    #pragma unroll 4
    for (int t = 0; t < Lv/32; t++) {
        int j = lane + (t << 5);
        float dx = xi - ca_s[j*3+0];
        float dy = yi - ca_s[j*3+1];
        float dz = zi - ca_s[j*3+2];
        float d  = sqrtf(dx*dx + dy*dy + dz*dz + 1e-6f);
        float D  = mi * mb[j] * d;
        dw[j] = D;
        lmax = fmaxf(lmax, D);
    }
    #pragma unroll
    for (int o = 16; o; o >>= 1) lmax = fmaxf(lmax, __shfl_xor_sync(0xffffffffu, lmax, o));
    float Dmax = lmax;

    // pass 2: D_adjust + initial lane-local min key
    unsigned long long lmin = ~0ULL;
    #pragma unroll 4
    for (int t = 0; t < Lv/32; t++) {
        int j = lane + (t << 5);
        float m2 = mi * mb[j];
        float Dadj = dw[j] + (1.0f - m2) * Dmax;
        dw[j] = Dadj;
        unsigned long long k = (((unsigned long long)__float_as_uint(Dadj)) << 32) | (unsigned)j;
        lmin = umin64(lmin, k);
    }

    // 32 selection rounds, shfl-only
    for (int r = 0; r < Kv; r++) {
        unsigned long long w = lmin;
        #pragma unroll
        for (int o = 16; o; o >>= 1) {
            unsigned long long v = __shfl_xor_sync(0xffffffffu, w, o);
            w = umin64(w, v);
        }
        int j = (int)(unsigned)(w & 0xffffffffu);
        if (lane == 0) {
            g_eidx[(size_t)row*Kv + r] = j;
            g_dn[(size_t)row*Kv + r]   = __uint_as_float((unsigned)(w >> 32));
        }
        if ((j & 31) == lane) {
            dw[j] = __int_as_float(0x7f800000);  // +inf
            lmin = ~0ULL;
            #pragma unroll 4
            for (int t = 0; t < Lv/32; t++) {
                int jj = lane + (t << 5);
                float Dv = dw[jj];
                unsigned long long k = (((unsigned long long)__float_as_uint(Dv)) << 32) | (unsigned)jj;
                lmin = umin64(lmin, k);
            }
        }
    }
}

// ---------------------------------------------------------------------------
// Kernel 3: per (b,i): build F[32][416] = [E_pos(16) | R0(16) | 24 x RBF16],
// GEMM F @ W_edge (416x128) with packed fma.rn.f32x2 (pairs over K dim),
// LayerNorm(128), write E (+ E_idx tail).
// 256 threads: 8 warps; warp w -> rows 4w..4w+3, lane -> 4 output columns.
// ---------------------------------------------------------------------------
__global__ void k3_edge(const int* __restrict__ ridx, const int* __restrict__ chl,
                        const float* __restrict__ Wpos, const float* __restrict__ bpos,
                        const float* __restrict__ Wedge,
                        const float* __restrict__ gamma, const float* __restrict__ beta,
                        float* __restrict__ out, int write_idx) {
    extern __shared__ float smem[];
    float* F   = smem;                 // 32*416
    float* qa  = F + Kv*FD;            // 16 (15 used)
    float* nbA = qa + 16;              // 32*15
    int*   jv  = (int*)(nbA + Kv*15);  // 32
    float* Dn  = (float*)(jv + Kv);    // 32
    int*  dpos = (int*)(Dn + Kv);      // 32

    int row = blockIdx.x;            // b*Lv + i
    int b   = row >> 11;
    int tid = threadIdx.x;

    if (tid < Kv) {
        int j = g_eidx[(size_t)row*Kv + tid];
        jv[tid] = j;
        Dn[tid] = g_dn[(size_t)row*Kv + tid];
        int off = ridx[row] - ridx[(size_t)b*Lv + j];
        int ech = (chl[row] == chl[(size_t)b*Lv + j]) ? 1 : 0;
        int d = off + 32;
        d = d < 0 ? 0 : (d > 64 ? 64 : d);
        dpos[tid] = ech ? d : 65;
    }
    if (tid < 15) qa[tid] = g_atoms[(size_t)row*15 + tid];
    __syncthreads();

    // gather neighbor atoms (32 neighbors x 5 atoms x 3)
    for (int t = tid; t < Kv*15; t += 256) {
        int k = t / 15, r2 = t % 15;
        nbA[t] = g_atoms[((size_t)b*Lv + jv[k])*15 + r2];
    }
    // positional embedding: F[k][0..15]
    for (int t = tid; t < Kv*16; t += 256) {
        int k = t >> 4, c = t & 15;
        F[k*FD + c] = Wpos[dpos[k]*16 + c] + bpos[c];
    }
    __syncthreads();

    // RBF groups: g=0 -> D_neighbors, g=1..24 -> atom-pair distances
    const float inv_sigma = 0.8f; // 1 / 1.25
    for (int t = tid; t < Kv*25; t += 256) {
        int k = t / 25, g = t % 25;
        float Dv;
        if (g == 0) {
            Dv = Dn[k];
        } else {
            int p = g - 1;
            const float* A  = qa  + c_PA[p]*3;
            const float* Bp = nbA + k*15 + c_PB[p]*3;
            float dx = A[0]-Bp[0], dy = A[1]-Bp[1], dz = A[2]-Bp[2];
            Dv = sqrtf(dx*dx + dy*dy + dz*dz + 1e-6f);
        }
        float* dst = F + k*FD + 16 + g*16;
        #pragma unroll
        for (int m = 0; m < 16; m++) {
            float mu = 2.0f + (float)m * (4.0f/3.0f);
            float z = (Dv - mu) * inv_sigma;
            dst[m] = __expf(-(z*z));
        }
    }
    __syncthreads();

    // GEMM with packed f32x2 FMAs: acc[r][c] holds the (even-f, odd-f)
    // partial sums packed in one 64-bit register; reduced lo+hi at the end.
    int warp = tid >> 5, lane = tid & 31;
    int c0 = lane * 4;
    unsigned long long acc[4][4];
    #pragma unroll
    for (int r = 0; r < 4; r++)
        #pragma unroll
        for (int c = 0; c < 4; c++) acc[r][c] = 0ULL;

    const float* Fw = F + (warp*4)*FD;
    #pragma unroll 2
    for (int f0 = 0; f0 < FD; f0 += 4) {
        // F pairs: contiguous in smem -> direct 64-bit pair loads
        ulonglong2 frp[4];
        #pragma unroll
        for (int r = 0; r < 4; r++)
            frp[r] = *(const ulonglong2*)(Fw + r*FD + f0);
        // W rows f0..f0+3, our 4 columns
        float4 w0 = *(const float4*)(Wedge + (size_t)(f0+0)*CD + c0);
        float4 w1 = *(const float4*)(Wedge + (size_t)(f0+1)*CD + c0);
        float4 w2 = *(const float4*)(Wedge + (size_t)(f0+2)*CD + c0);
        float4 w3 = *(const float4*)(Wedge + (size_t)(f0+3)*CD + c0);
        unsigned long long wp0[4] = { pk2(w0.x,w1.x), pk2(w0.y,w1.y), pk2(w0.z,w1.z), pk2(w0.w,w1.w) };
        unsigned long long wp1[4] = { pk2(w2.x,w3.x), pk2(w2.y,w3.y), pk2(w2.z,w3.z), pk2(w2.w,w3.w) };
        #pragma unroll
        for (int r = 0; r < 4; r++) {
            #pragma unroll
            for (int c = 0; c < 4; c++) {
                ffma2(acc[r][c], frp[r].x, wp0[c]);
                ffma2(acc[r][c], frp[r].y, wp1[c]);
            }
        }
    }

    // LayerNorm per row (128 values spread across the warp, 4 per lane)
    float4 gv = *(const float4*)(gamma + c0);
    float4 bv = *(const float4*)(beta + c0);
    #pragma unroll
    for (int r = 0; r < 4; r++) {
        float v[4];
        #pragma unroll
        for (int c = 0; c < 4; c++) {
            float lo, hi; upk2(acc[r][c], lo, hi);
            v[c] = lo + hi;
        }
        float s = v[0] + v[1] + v[2] + v[3];
        #pragma unroll
        for (int o = 16; o; o >>= 1) s += __shfl_xor_sync(0xffffffffu, s, o);
        float mu = s * (1.0f/128.0f);
        float d0 = v[0]-mu, d1 = v[1]-mu, d2 = v[2]-mu, d3 = v[3]-mu;
        float ss = d0*d0 + d1*d1 + d2*d2 + d3*d3;
        #pragma unroll
        for (int o = 16; o; o >>= 1) ss += __shfl_xor_sync(0xffffffffu, ss, o);
        float var = ss * (1.0f/128.0f);
        float inv = 1.0f / sqrtf(var + 1e-5f);
        int k = warp*4 + r;
        float4 res;
        res.x = d0*inv*gv.x + bv.x;
        res.y = d1*inv*gv.y + bv.y;
        res.z = d2*inv*gv.z + bv.z;
        res.w = d3*inv*gv.w + bv.w;
        *(float4*)(out + (((size_t)row*Kv + k)*CD + c0)) = res;
    }

    if (write_idx && tid < Kv) {
        out[(size_t)Bv*Lv*Kv*CD + (size_t)row*Kv + tid] = (float)jv[tid];
    }
}

// ---------------------------------------------------------------------------
// Launch
// ---------------------------------------------------------------------------
extern "C" void kernel_launch(void* const* d_in, const int* in_sizes, int n_in,
                              void* d_out, int out_size) {
    const float* X     = (const float*)d_in[0];
    const float* mask  = (const float*)d_in[1];
    const int*   ridx  = (const int*)  d_in[2];
    const int*   chl   = (const int*)  d_in[3];
    const float* Wpos  = (const float*)d_in[4];
    const float* bpos  = (const float*)d_in[5];
    const float* Wedge = (const float*)d_in[6];
    const float* gamma = (const float*)d_in[7];
    const float* beta  = (const float*)d_in[8];
    float* out = (float*)d_out;

    const int k2_smem = (Lv*3 + 8*Lv) * 4;                    // 90112 B
    const int k3_smem = (Kv*FD + 16 + Kv*15 + Kv*3) * 4;      // 55616 B
    cudaFuncSetAttribute(k2_topk, cudaFuncAttributeMaxDynamicSharedMemorySize, k2_smem);
    cudaFuncSetAttribute(k3_edge, cudaFuncAttributeMaxDynamicSharedMemorySize, k3_smem);

    k1_atoms<<<(Bv*Lv + 255)/256, 256>>>(X);
    k2_topk<<<Bv*Lv/8, 256, k2_smem>>>(mask);

    long long e_elems = (long long)Bv*Lv*Kv*CD;
    int write_idx = ((long long)out_size >= e_elems + (long long)Bv*Lv*Kv) ? 1 : 0;
    k3_edge<<<Bv*Lv, 256, k3_smem>>>(ridx, chl, Wpos, bpos, Wedge, gamma, beta, out, write_idx);
}

// round 5
// speedup vs baseline: 2.3748x; 2.3748x over previous
#include <cuda_runtime.h>
#include <cuda_bf16.h>
#include <cstdint>
#include <math.h>

#define Bv 4
#define Lv 2048
#define Kv 32
#define CD 128
#define KPAD 448        // 416 padded to 7*64
#define NCH 7           // K chunks of 64
#define STRD 72         // bf16 elems per row in tiles (144 B, 9x16B -> conflict-free LDSM)
#define CHUNK_U4 1152   // 128 rows * 144 B / 16
#define GRID3 (Bv*Lv/4) // 2048 CTAs, 4 residues (128 edges) each

// Scratch (__device__ globals; no allocation allowed)
__device__ float g_atoms[Bv*Lv*5*3];
__device__ float g_ca[Bv*Lv*3];
__device__ int   g_eidx[Bv*Lv*Kv];
__device__ float g_dn[Bv*Lv*Kv];
__device__ uint4 g_WtHi[NCH*CHUNK_U4];   // W^T bf16 hi, [chunk][n=128][k=64] stride 72
__device__ uint4 g_WtLo[NCH*CHUNK_U4];   // W^T bf16 lo

__constant__ int c_PA[24] = {0,2,3,4,1,1,1,1,0,0,0,4,4,3,0,2,3,4,2,3,4,2,3,2};
__constant__ int c_PB[24] = {0,2,3,4,0,2,3,4,2,3,4,2,3,2,1,1,1,1,0,0,0,4,4,3};

__device__ __forceinline__ unsigned smem_u32(const void* p) {
    unsigned a;
    asm("{ .reg .u64 t; cvta.to.shared.u64 t, %1; cvt.u32.u64 %0, t; }" : "=r"(a) : "l"(p));
    return a;
}
__device__ __forceinline__ void ldsm4(unsigned* r, unsigned addr) {
    asm volatile("ldmatrix.sync.aligned.m8n8.x4.shared.b16 {%0,%1,%2,%3}, [%4];"
        : "=r"(r[0]), "=r"(r[1]), "=r"(r[2]), "=r"(r[3]) : "r"(addr));
}
__device__ __forceinline__ void mma16816(float* c, const unsigned* a, unsigned b0, unsigned b1) {
    asm volatile("mma.sync.aligned.m16n8k16.row.col.f32.bf16.bf16.f32 "
        "{%0,%1,%2,%3},{%4,%5,%6,%7},{%8,%9},{%0,%1,%2,%3};"
        : "+f"(c[0]), "+f"(c[1]), "+f"(c[2]), "+f"(c[3])
        : "r"(a[0]), "r"(a[1]), "r"(a[2]), "r"(a[3]), "r"(b0), "r"(b1));
}

// ---------------------------------------------------------------------------
// k0: W_edge (416x128 f32) -> bf16 hi/lo tiles: [chunk][n][k], row stride 72
// ---------------------------------------------------------------------------
__global__ void k0_prepW(const float* __restrict__ W) {
    int idx = blockIdx.x * 256 + threadIdx.x;     // KPAD*128 = 57344
    if (idx >= KPAD * CD) return;
    int f = idx >> 7, n = idx & 127;
    float w = (f < 416) ? W[f * CD + n] : 0.0f;
    __nv_bfloat16 h = __float2bfloat16(w);
    __nv_bfloat16 l = __float2bfloat16(w - __bfloat162float(h));
    int kc = f >> 6, kk = f & 63;
    size_t off = (size_t)(kc * 128 + n) * STRD + kk;
    ((__nv_bfloat16*)g_WtHi)[off] = h;
    ((__nv_bfloat16*)g_WtLo)[off] = l;
}

// ---------------------------------------------------------------------------
// k1: atom table (N, Ca, C, O, Cb)
// ---------------------------------------------------------------------------
__global__ void k1_atoms(const float* __restrict__ X) {
    int i = blockIdx.x * blockDim.x + threadIdx.x;
    if (i >= Bv*Lv) return;
    const float* x = X + (size_t)i * 12;
    float Nx=x[0],Ny=x[1],Nz=x[2];
    float Ax=x[3],Ay=x[4],Az=x[5];
    float Cx=x[6],Cy=x[7],Cz=x[8];
    float Ox=x[9],Oy=x[10],Oz=x[11];
    float bx=Ax-Nx, by=Ay-Ny, bz=Az-Nz;
    float cx=Cx-Ax, cy=Cy-Ay, cz=Cz-Az;
    float ax=by*cz-bz*cy, ay=bz*cx-bx*cz, az=bx*cy-by*cx;
    float Cbx = -0.58273431f*ax + 0.56802827f*bx - 0.54067466f*cx + Ax;
    float Cby = -0.58273431f*ay + 0.56802827f*by - 0.54067466f*cy + Ay;
    float Cbz = -0.58273431f*az + 0.56802827f*bz - 0.54067466f*cz + Az;
    float* p = g_atoms + (size_t)i * 15;
    p[0]=Nx; p[1]=Ny; p[2]=Nz;
    p[3]=Ax; p[4]=Ay; p[5]=Az;
    p[6]=Cx; p[7]=Cy; p[8]=Cz;
    p[9]=Ox; p[10]=Oy; p[11]=Oz;
    p[12]=Cbx; p[13]=Cby; p[14]=Cbz;
    g_ca[i*3+0]=Ax; g_ca[i*3+1]=Ay; g_ca[i*3+2]=Az;
}

// ---------------------------------------------------------------------------
// k2: top-K per row (proven R1 version: one 256-thread block per row)
// ---------------------------------------------------------------------------
__device__ __forceinline__ unsigned long long umin64(unsigned long long a, unsigned long long b) {
    return a < b ? a : b;
}
__global__ void k2_topk(const float* __restrict__ mask) {
    extern __shared__ char smem_raw[];
    float* ca_s = (float*)smem_raw;
    float* d_s  = ca_s + Lv*3;
    unsigned long long* key_s = (unsigned long long*)(d_s + Lv);

    __shared__ float s_red[8];
    __shared__ unsigned long long s_wmin[8];
    __shared__ unsigned long long s_chosen;
    __shared__ float s_dmax;

    int row = blockIdx.x;
    int b   = row >> 11;
    int tid = threadIdx.x;

    const float* cab = g_ca + (size_t)b * Lv * 3;
    for (int idx = tid; idx < Lv*3; idx += 256) ca_s[idx] = cab[idx];
    __syncthreads();

    int li = row & (Lv-1);
    float xi = ca_s[li*3+0], yi = ca_s[li*3+1], zi = ca_s[li*3+2];
    float mi = mask[row];
    const float* mb = mask + (size_t)b * Lv;

    float lmax = 0.0f;
    for (int j = tid; j < Lv; j += 256) {
        float dx = xi - ca_s[j*3+0];
        float dy = yi - ca_s[j*3+1];
        float dz = zi - ca_s[j*3+2];
        float d  = sqrtf(dx*dx + dy*dy + dz*dz + 1e-6f);
        float D  = mi * mb[j] * d;
        d_s[j] = D;
        lmax = fmaxf(lmax, D);
    }
    #pragma unroll
    for (int o = 16; o; o >>= 1) lmax = fmaxf(lmax, __shfl_down_sync(0xffffffffu, lmax, o));
    if ((tid & 31) == 0) s_red[tid >> 5] = lmax;
    __syncthreads();
    if (tid == 0) {
        float m = s_red[0];
        #pragma unroll
        for (int w = 1; w < 8; w++) m = fmaxf(m, s_red[w]);
        s_dmax = m;
    }
    __syncthreads();
    float Dmax = s_dmax;

    for (int j = tid; j < Lv; j += 256) {
        float m2 = mi * mb[j];
        float Dadj = d_s[j] + (1.0f - m2) * Dmax;
        key_s[j] = (((unsigned long long)__float_as_uint(Dadj)) << 32) | (unsigned)j;
    }
    __syncthreads();

    int base = tid * 8;
    unsigned long long lmin = ~0ULL;
    #pragma unroll
    for (int s = 0; s < 8; s++) lmin = umin64(lmin, key_s[base + s]);

    for (int r = 0; r < Kv; r++) {
        unsigned long long w = lmin;
        #pragma unroll
        for (int o = 16; o; o >>= 1) {
            unsigned long long v = __shfl_down_sync(0xffffffffu, w, o);
            w = umin64(w, v);
        }
        if ((tid & 31) == 0) s_wmin[tid >> 5] = w;
        __syncthreads();
        if (tid == 0) {
            unsigned long long m = s_wmin[0];
            #pragma unroll
            for (int q = 1; q < 8; q++) m = umin64(m, s_wmin[q]);
            s_chosen = m;
        }
        __syncthreads();
        unsigned long long ch = s_chosen;
        int j = (int)(unsigned)(ch & 0xffffffffu);
        if (tid == 0) {
            g_eidx[(size_t)row*Kv + r] = j;
            g_dn[(size_t)row*Kv + r]   = __uint_as_float((unsigned)(ch >> 32));
        }
        if ((j >> 3) == tid) {
            key_s[j] = ~0ULL;
            lmin = ~0ULL;
            #pragma unroll
            for (int s = 0; s < 8; s++) lmin = umin64(lmin, key_s[base + s]);
        }
        __syncthreads();
    }
}

// ---------------------------------------------------------------------------
// k3: fused feature-build + mma.sync bf16 hi/lo GEMM + LayerNorm.
// CTA = 4 residues x 32 nbrs = 128 edges. Warp w owns edge rows 16w..16w+15.
// K chunks of 64; per chunk: build A hi/lo in smem, copy B hi/lo, 4 k-steps
// of m16n8k16 with 3 accumulation passes (AhBh, AlBh, AhBl).
// ---------------------------------------------------------------------------
#define S_AH  0
#define S_AL  18432
#define S_BH  36864
#define S_BL  55296
#define S_NBA 73728                       // 128*15 f32 = 7680
#define S_QA  (S_NBA + 7680)              // 60 f32
#define S_JV  (S_QA + 240)                // 128 int
#define S_DN  (S_JV + 512)                // 128 f32
#define S_DP  (S_DN + 512)                // 128 int
#define S_TOT (S_DP + 512)                // 83184 B

__global__ void __launch_bounds__(256)
k3_mma(const int* __restrict__ ridx, const int* __restrict__ chl,
       const float* __restrict__ Wpos, const float* __restrict__ bpos,
       const float* __restrict__ gamma, const float* __restrict__ beta,
       float* __restrict__ out, int write_idx) {
    extern __shared__ unsigned char sm[];
    unsigned sb = smem_u32(sm);
    int tid  = threadIdx.x;
    int wid  = tid >> 5, lane = tid & 31;
    int row0 = blockIdx.x * 4;
    int b    = row0 >> 11;

    float* nbA  = (float*)(sm + S_NBA);
    float* qa   = (float*)(sm + S_QA);
    int*   jv   = (int*)  (sm + S_JV);
    float* Dn   = (float*)(sm + S_DN);
    int*   dpos = (int*)  (sm + S_DP);

    // phase 1: per-edge scalars + query atoms
    if (tid < 128) {
        int r = tid >> 5;
        int brow = row0 + r;
        int j = g_eidx[(size_t)row0*Kv + tid];
        jv[tid] = j;
        Dn[tid] = g_dn[(size_t)row0*Kv + tid];
        int off = ridx[brow] - ridx[(size_t)b*Lv + j];
        int ech = (chl[brow] == chl[(size_t)b*Lv + j]) ? 1 : 0;
        int d = off + 32;
        d = d < 0 ? 0 : (d > 64 ? 64 : d);
        dpos[tid] = ech ? d : 65;
    }
    if (tid >= 160 && tid < 220) {
        int t = tid - 160;
        qa[t] = g_atoms[(size_t)(row0 + t/15)*15 + (t%15)];
    }
    __syncthreads();

    // phase 2: neighbor atom gather
    for (int t = tid; t < 128*15; t += 256) {
        nbA[t] = g_atoms[((size_t)b*Lv + jv[t/15])*15 + (t%15)];
    }
    __syncthreads();

    int e  = tid & 127;
    int s0 = tid >> 7;
    int r  = e >> 5;

    float acc[16][4];
    #pragma unroll
    for (int nt = 0; nt < 16; nt++) {
        acc[nt][0]=0.f; acc[nt][1]=0.f; acc[nt][2]=0.f; acc[nt][3]=0.f;
    }

    unsigned aBaseH = sb + S_AH + (unsigned)(wid*16)*144;
    unsigned aBaseL = sb + S_AL + (unsigned)(wid*16)*144;
    int arow  = lane & 15;
    int acol8 = (lane >> 4) * 8;

    for (int kc = 0; kc < NCH; kc++) {
        // B chunk copy (contiguous 18432 B each)
        {
            const uint4* shi = g_WtHi + kc*CHUNK_U4;
            const uint4* slo = g_WtLo + kc*CHUNK_U4;
            uint4* dhi = (uint4*)(sm + S_BH);
            uint4* dlo = (uint4*)(sm + S_BL);
            for (int i = tid; i < CHUNK_U4; i += 256) {
                dhi[i] = shi[i];
                dlo[i] = slo[i];
            }
        }
        // A chunk build: thread handles edge e, sub-blocks ss = s0, s0+2 (16 k each)
        #pragma unroll
        for (int pp = 0; pp < 2; pp++) {
            int ss = s0 + pp*2;
            int S  = kc*4 + ss;
            float vals[16];
            if (S == 0) {
                const float4* wp = (const float4*)(Wpos + dpos[e]*16);
                const float4* bb = (const float4*)bpos;
                #pragma unroll
                for (int q = 0; q < 4; q++) {
                    float4 a = wp[q], c = bb[q];
                    vals[q*4+0]=a.x+c.x; vals[q*4+1]=a.y+c.y; vals[q*4+2]=a.z+c.z; vals[q*4+3]=a.w+c.w;
                }
            } else if (S < 26) {
                float D;
                if (S == 1) D = Dn[e];
                else {
                    int p = S - 2;
                    const float* A  = qa  + r*15 + c_PA[p]*3;
                    const float* Bp = nbA + e*15 + c_PB[p]*3;
                    float dx=A[0]-Bp[0], dy=A[1]-Bp[1], dz=A[2]-Bp[2];
                    D = sqrtf(dx*dx + dy*dy + dz*dz + 1e-6f);
                }
                #pragma unroll
                for (int m = 0; m < 16; m++) {
                    float mu = 2.0f + (float)m * (4.0f/3.0f);
                    float z = (D - mu) * 0.8f;
                    vals[m] = __expf(-(z*z));
                }
            } else {
                #pragma unroll
                for (int m = 0; m < 16; m++) vals[m] = 0.0f;
            }
            // pack bf16 hi/lo, write 2x uint4 each
            unsigned byteoff = (unsigned)e*144 + (unsigned)ss*32;
            #pragma unroll
            for (int q = 0; q < 2; q++) {
                unsigned hp[4], lp[4];
                #pragma unroll
                for (int j4 = 0; j4 < 4; j4++) {
                    float v0 = vals[q*8 + j4*2], v1 = vals[q*8 + j4*2 + 1];
                    __nv_bfloat16 h0 = __float2bfloat16(v0);
                    __nv_bfloat16 h1 = __float2bfloat16(v1);
                    __nv_bfloat16 l0 = __float2bfloat16(v0 - __bfloat162float(h0));
                    __nv_bfloat16 l1 = __float2bfloat16(v1 - __bfloat162float(h1));
                    hp[j4] = ((unsigned)__bfloat16_as_ushort(h1) << 16) | __bfloat16_as_ushort(h0);
                    lp[j4] = ((unsigned)__bfloat16_as_ushort(l1) << 16) | __bfloat16_as_ushort(l0);
                }
                *(uint4*)(sm + S_AH + byteoff + q*16) = make_uint4(hp[0],hp[1],hp[2],hp[3]);
                *(uint4*)(sm + S_AL + byteoff + q*16) = make_uint4(lp[0],lp[1],lp[2],lp[3]);
            }
        }
        __syncthreads();

        // MMA: 4 k-steps of 16
        #pragma unroll
        for (int ks = 0; ks < 4; ks++) {
            int k0 = ks * 16;
            unsigned ah[4], al[4];
            ldsm4(ah, aBaseH + (unsigned)arow*144 + (unsigned)(k0 + acol8)*2);
            ldsm4(al, aBaseL + (unsigned)arow*144 + (unsigned)(k0 + acol8)*2);
            #pragma unroll
            for (int qg = 0; qg < 4; qg++) {
                unsigned bh0[4], bh1[4], bl0[4], bl1[4];
                unsigned boffH = sb + S_BH + (unsigned)(qg*32 + lane)*144 + (unsigned)k0*2;
                unsigned boffL = sb + S_BL + (unsigned)(qg*32 + lane)*144 + (unsigned)k0*2;
                ldsm4(bh0, boffH);
                ldsm4(bh1, boffH + 16);
                ldsm4(bl0, boffL);
                ldsm4(bl1, boffL + 16);
                #pragma unroll
                for (int m = 0; m < 4; m++) {
                    int nt = qg*4 + m;
                    mma16816(acc[nt], ah, bh0[m], bh1[m]);
                    mma16816(acc[nt], al, bh0[m], bh1[m]);
                    mma16816(acc[nt], ah, bl0[m], bl1[m]);
                }
            }
        }
        __syncthreads();
    }

    // E_idx tail
    if (write_idx && tid < 128) {
        out[(size_t)Bv*Lv*Kv*CD + (size_t)row0*Kv + tid] = (float)jv[tid];
    }

    // epilogue: LayerNorm per edge row. Lane holds cols nt*8+2*(lane&3)+{0,1}
    // for local rows rA = lane>>2 and rB = rA+8.
    {
        int rA = lane >> 2;
        float s1a=0.f, s2a=0.f, s1b=0.f, s2b=0.f;
        #pragma unroll
        for (int nt = 0; nt < 16; nt++) {
            float v0 = acc[nt][0], v1 = acc[nt][1];
            float v2 = acc[nt][2], v3 = acc[nt][3];
            s1a += v0 + v1;  s2a += v0*v0 + v1*v1;
            s1b += v2 + v3;  s2b += v2*v2 + v3*v3;
        }
        #pragma unroll
        for (int o = 1; o <= 2; o <<= 1) {
            s1a += __shfl_xor_sync(0xffffffffu, s1a, o);
            s2a += __shfl_xor_sync(0xffffffffu, s2a, o);
            s1b += __shfl_xor_sync(0xffffffffu, s1b, o);
            s2b += __shfl_xor_sync(0xffffffffu, s2b, o);
        }
        float muA = s1a * (1.0f/128.0f);
        float vrA = s2a * (1.0f/128.0f) - muA*muA;
        float ivA = 1.0f / sqrtf(vrA + 1e-5f);
        float muB = s1b * (1.0f/128.0f);
        float vrB = s2b * (1.0f/128.0f) - muB*muB;
        float ivB = 1.0f / sqrtf(vrB + 1e-5f);

        int eA = wid*16 + rA;            // local edge rows
        int eB = eA + 8;
        float* opA = out + ((size_t)row0*Kv + eA) * CD;   // row0*Kv + e == global edge
        float* opB = out + ((size_t)row0*Kv + eB) * CD;
        int cbase = 2*(lane & 3);
        #pragma unroll
        for (int nt = 0; nt < 16; nt++) {
            int c = nt*8 + cbase;
            float g0 = gamma[c], g1 = gamma[c+1];
            float b0 = beta[c],  b1 = beta[c+1];
            float2 oA, oB;
            oA.x = (acc[nt][0] - muA)*ivA*g0 + b0;
            oA.y = (acc[nt][1] - muA)*ivA*g1 + b1;
            oB.x = (acc[nt][2] - muB)*ivB*g0 + b0;
            oB.y = (acc[nt][3] - muB)*ivB*g1 + b1;
            *(float2*)(opA + c) = oA;
            *(float2*)(opB + c) = oB;
        }
    }
}

// ---------------------------------------------------------------------------
// Launch
// ---------------------------------------------------------------------------
extern "C" void kernel_launch(void* const* d_in, const int* in_sizes, int n_in,
                              void* d_out, int out_size) {
    const float* X     = (const float*)d_in[0];
    const float* mask  = (const float*)d_in[1];
    const int*   ridx  = (const int*)  d_in[2];
    const int*   chl   = (const int*)  d_in[3];
    const float* Wpos  = (const float*)d_in[4];
    const float* bpos  = (const float*)d_in[5];
    const float* Wedge = (const float*)d_in[6];
    const float* gamma = (const float*)d_in[7];
    const float* beta  = (const float*)d_in[8];
    float* out = (float*)d_out;

    const int k2_smem = (Lv*3 + Lv)*4 + Lv*8;
    cudaFuncSetAttribute(k2_topk, cudaFuncAttributeMaxDynamicSharedMemorySize, k2_smem);
    cudaFuncSetAttribute(k3_mma,  cudaFuncAttributeMaxDynamicSharedMemorySize, S_TOT);

    k0_prepW<<<(KPAD*CD + 255)/256, 256>>>(Wedge);
    k1_atoms<<<(Bv*Lv + 255)/256, 256>>>(X);
    k2_topk<<<Bv*Lv, 256, k2_smem>>>(mask);

    long long e_elems = (long long)Bv*Lv*Kv*CD;
    int write_idx = ((long long)out_size >= e_elems + (long long)Bv*Lv*Kv) ? 1 : 0;
    k3_mma<<<GRID3, 256, S_TOT>>>(ridx, chl, Wpos, bpos, gamma, beta, out, write_idx);
}

// round 6
// speedup vs baseline: 3.5251x; 1.4844x over previous
#include <cuda_runtime.h>
#include <cuda_bf16.h>
#include <cstdint>
#include <math.h>

#define Bv 4
#define Lv 2048
#define Kv 32
#define CD 128
#define KPAD 448        // 416 padded to 7*64
#define NCH 7           // K chunks of 64
#define STRD 72         // bf16 elems per row in tiles (144 B, 9x16B -> conflict-free LDSM)
#define CHUNK_U4 1152   // 128 rows * 144 B / 16
#define GRID3 (Bv*Lv/4) // 2048 CTAs, 4 residues (128 edges) each

// Scratch (__device__ globals; no allocation allowed)
__device__ float g_atoms[Bv*Lv*5*3];
__device__ float g_ca[Bv*Lv*3];
__device__ int   g_eidx[Bv*Lv*Kv];
__device__ float g_dn[Bv*Lv*Kv];
__device__ uint4 g_WtHi[NCH*CHUNK_U4];   // W^T bf16 hi, [chunk][n=128][k=64] stride 72
__device__ uint4 g_WtLo[NCH*CHUNK_U4];   // W^T bf16 lo

__constant__ int c_PA[24] = {0,2,3,4,1,1,1,1,0,0,0,4,4,3,0,2,3,4,2,3,4,2,3,2};
__constant__ int c_PB[24] = {0,2,3,4,0,2,3,4,2,3,4,2,3,2,1,1,1,1,0,0,0,4,4,3};

__device__ __forceinline__ unsigned smem_u32(const void* p) {
    unsigned a;
    asm("{ .reg .u64 t; cvta.to.shared.u64 t, %1; cvt.u32.u64 %0, t; }" : "=r"(a) : "l"(p));
    return a;
}
__device__ __forceinline__ void ldsm4(unsigned* r, unsigned addr) {
    asm volatile("ldmatrix.sync.aligned.m8n8.x4.shared.b16 {%0,%1,%2,%3}, [%4];"
        : "=r"(r[0]), "=r"(r[1]), "=r"(r[2]), "=r"(r[3]) : "r"(addr));
}
__device__ __forceinline__ void mma16816(float* c, const unsigned* a, unsigned b0, unsigned b1) {
    asm volatile("mma.sync.aligned.m16n8k16.row.col.f32.bf16.bf16.f32 "
        "{%0,%1,%2,%3},{%4,%5,%6,%7},{%8,%9},{%0,%1,%2,%3};"
        : "+f"(c[0]), "+f"(c[1]), "+f"(c[2]), "+f"(c[3])
        : "r"(a[0]), "r"(a[1]), "r"(a[2]), "r"(a[3]), "r"(b0), "r"(b1));
}
__device__ __forceinline__ unsigned cvt_bf16x2(float hi, float lo) {
    unsigned r;
    asm("cvt.rn.bf16x2.f32 %0, %1, %2;" : "=r"(r) : "f"(hi), "f"(lo));
    return r;
}
__device__ __forceinline__ unsigned long long umin64(unsigned long long a, unsigned long long b) {
    return a < b ? a : b;
}

// ---------------------------------------------------------------------------
// k0: W_edge (416x128 f32) -> bf16 hi/lo tiles: [chunk][n][k], row stride 72
// ---------------------------------------------------------------------------
__global__ void k0_prepW(const float* __restrict__ W) {
    int idx = blockIdx.x * 256 + threadIdx.x;     // KPAD*128 = 57344
    if (idx >= KPAD * CD) return;
    int f = idx >> 7, n = idx & 127;
    float w = (f < 416) ? W[f * CD + n] : 0.0f;
    __nv_bfloat16 h = __float2bfloat16(w);
    __nv_bfloat16 l = __float2bfloat16(w - __bfloat162float(h));
    int kc = f >> 6, kk = f & 63;
    size_t off = (size_t)(kc * 128 + n) * STRD + kk;
    ((__nv_bfloat16*)g_WtHi)[off] = h;
    ((__nv_bfloat16*)g_WtLo)[off] = l;
}

// ---------------------------------------------------------------------------
// k1: atom table (N, Ca, C, O, Cb)
// ---------------------------------------------------------------------------
__global__ void k1_atoms(const float* __restrict__ X) {
    int i = blockIdx.x * blockDim.x + threadIdx.x;
    if (i >= Bv*Lv) return;
    const float* x = X + (size_t)i * 12;
    float Nx=x[0],Ny=x[1],Nz=x[2];
    float Ax=x[3],Ay=x[4],Az=x[5];
    float Cx=x[6],Cy=x[7],Cz=x[8];
    float Ox=x[9],Oy=x[10],Oz=x[11];
    float bx=Ax-Nx, by=Ay-Ny, bz=Az-Nz;
    float cx=Cx-Ax, cy=Cy-Ay, cz=Cz-Az;
    float ax=by*cz-bz*cy, ay=bz*cx-bx*cz, az=bx*cy-by*cx;
    float Cbx = -0.58273431f*ax + 0.56802827f*bx - 0.54067466f*cx + Ax;
    float Cby = -0.58273431f*ay + 0.56802827f*by - 0.54067466f*cy + Ay;
    float Cbz = -0.58273431f*az + 0.56802827f*bz - 0.54067466f*cz + Az;
    float* p = g_atoms + (size_t)i * 15;
    p[0]=Nx; p[1]=Ny; p[2]=Nz;
    p[3]=Ax; p[4]=Ay; p[5]=Az;
    p[6]=Cx; p[7]=Cy; p[8]=Cz;
    p[9]=Ox; p[10]=Oy; p[11]=Oz;
    p[12]=Cbx; p[13]=Cby; p[14]=Cbz;
    g_ca[i*3+0]=Ax; g_ca[i*3+1]=Ay; g_ca[i*3+2]=Az;
}

// ---------------------------------------------------------------------------
// k2: top-K, 4 rows per 256-thread CTA. Phase A: all threads compute the
// distances (thread owns 8 contiguous columns for all 4 rows), per-row Dmax
// via warp reduce + smem atomicMax, per-thread min-key staged to smem.
// Phase B: warps 0-3 (one per row, one per SMSP) run 32 shfl-only selection
// rounds; on invalidation the owning lane rescans that thread's 8 entries.
// Key = (float_bits(D_adjust)<<32) | j  reproduces jax.lax.top_k ordering.
// ---------------------------------------------------------------------------
__global__ void __launch_bounds__(256)
k2_topk(const float* __restrict__ mask) {
    extern __shared__ char smem_raw[];
    float* ca_s = (float*)smem_raw;                                   // 2048*3 f32 (24KB)
    float* d_s  = ca_s + Lv*3;                                        // 4*2048 f32 (32KB)
    unsigned long long* tmin = (unsigned long long*)(d_s + 4*Lv);     // 4*256 u64 (8KB)
    __shared__ int s_maxi[4];

    int tid  = threadIdx.x;
    int wid  = tid >> 5, lane = tid & 31;
    int row0 = blockIdx.x * 4;
    int b    = row0 >> 11;

    if (tid < 4) s_maxi[tid] = 0;
    const float* cab = g_ca + (size_t)b * Lv * 3;
    for (int i = tid; i < Lv*3; i += 256) ca_s[i] = cab[i];
    __syncthreads();

    // row centers + masks
    float cx[4], cy[4], cz[4], mi[4];
    #pragma unroll
    for (int r = 0; r < 4; r++) {
        int li = (row0 + r) & (Lv-1);
        cx[r] = ca_s[li*3+0]; cy[r] = ca_s[li*3+1]; cz[r] = ca_s[li*3+2];
        mi[r] = mask[(size_t)row0 + r];
    }
    const float* mb = mask + (size_t)b * Lv;

    // distances: thread owns columns j0..j0+7 for all 4 rows
    int j0 = tid * 8;
    float Dreg[4][8], mbj[8];
    float lmax[4] = {0.f, 0.f, 0.f, 0.f};
    #pragma unroll
    for (int s = 0; s < 8; s++) {
        int j = j0 + s;
        float px = ca_s[j*3+0], py = ca_s[j*3+1], pz = ca_s[j*3+2];
        mbj[s] = mb[j];
        #pragma unroll
        for (int r = 0; r < 4; r++) {
            float dx = cx[r]-px, dy = cy[r]-py, dz = cz[r]-pz;
            float d  = sqrtf(dx*dx + dy*dy + dz*dz + 1e-6f);
            float D  = mi[r] * mbj[s] * d;
            Dreg[r][s] = D;
            lmax[r] = fmaxf(lmax[r], D);
        }
    }
    #pragma unroll
    for (int r = 0; r < 4; r++) {
        float v = lmax[r];
        #pragma unroll
        for (int o = 16; o; o >>= 1) v = fmaxf(v, __shfl_xor_sync(0xffffffffu, v, o));
        if (lane == 0) atomicMax(&s_maxi[r], __float_as_int(v));
    }
    __syncthreads();

    // D_adjust + per-thread min key per row
    #pragma unroll
    for (int r = 0; r < 4; r++) {
        float Dmax = __int_as_float(s_maxi[r]);
        unsigned long long mn = ~0ULL;
        #pragma unroll
        for (int s = 0; s < 8; s++) {
            int j = j0 + s;
            float m2 = mi[r] * mbj[s];
            float Dadj = Dreg[r][s] + (1.0f - m2) * Dmax;
            d_s[r*Lv + j] = Dadj;
            unsigned long long k = (((unsigned long long)__float_as_uint(Dadj)) << 32) | (unsigned)j;
            mn = umin64(mn, k);
        }
        tmin[r*256 + tid] = mn;
    }
    __syncthreads();

    // selection: warp r handles row r (no barriers)
    if (wid < 4) {
        int r = wid;
        int row = row0 + r;
        float* dr = d_s + r*Lv;
        unsigned long long m[8];
        #pragma unroll
        for (int s = 0; s < 8; s++) m[s] = tmin[r*256 + lane*8 + s];

        for (int rnd = 0; rnd < Kv; rnd++) {
            unsigned long long w = m[0];
            #pragma unroll
            for (int s = 1; s < 8; s++) w = umin64(w, m[s]);
            #pragma unroll
            for (int o = 16; o; o >>= 1) {
                unsigned long long v = __shfl_xor_sync(0xffffffffu, w, o);
                w = umin64(w, v);
            }
            int j = (int)(unsigned)(w & 0xffffffffu);
            if (lane == 0) {
                g_eidx[(size_t)row*Kv + rnd] = j;
                g_dn[(size_t)row*Kv + rnd]   = __uint_as_float((unsigned)(w >> 32));
            }
            int t = j >> 3;                   // owning thread slot
            if ((t >> 3) == lane) {           // owning lane rescans
                dr[j] = __int_as_float(0x7f800000);
                unsigned long long nm = ~0ULL;
                #pragma unroll
                for (int s = 0; s < 8; s++) {
                    int jj = t*8 + s;
                    float Dv = dr[jj];
                    unsigned long long k = (((unsigned long long)__float_as_uint(Dv)) << 32) | (unsigned)jj;
                    nm = umin64(nm, k);
                }
                m[t & 7] = nm;
            }
        }
    }
}

// ---------------------------------------------------------------------------
// k3: fused feature-build + mma.sync bf16 hi/lo GEMM + LayerNorm.
// CTA = 4 residues x 32 nbrs = 128 edges. Warp w owns edge rows 16w..16w+15.
// K chunks of 64; per chunk: build A hi/lo in smem, copy B hi/lo, k-steps
// of m16n8k16 with 3 accumulation passes (AhBh, AlBh, AhBl).
// Chunk 6 holds only 32 real features -> 2 k-steps, zero sub-blocks skipped.
// ---------------------------------------------------------------------------
#define S_AH  0
#define S_AL  18432
#define S_BH  36864
#define S_BL  55296
#define S_NBA 73728                       // 128*15 f32 = 7680
#define S_QA  (S_NBA + 7680)              // 60 f32
#define S_JV  (S_QA + 240)                // 128 int
#define S_DN  (S_JV + 512)                // 128 f32
#define S_DP  (S_DN + 512)                // 128 int
#define S_TOT (S_DP + 512)                // 83184 B

__global__ void __launch_bounds__(256)
k3_mma(const int* __restrict__ ridx, const int* __restrict__ chl,
       const float* __restrict__ Wpos, const float* __restrict__ bpos,
       const float* __restrict__ gamma, const float* __restrict__ beta,
       float* __restrict__ out, int write_idx) {
    extern __shared__ unsigned char sm[];
    unsigned sb = smem_u32(sm);
    int tid  = threadIdx.x;
    int wid  = tid >> 5, lane = tid & 31;
    int row0 = blockIdx.x * 4;
    int b    = row0 >> 11;

    float* nbA  = (float*)(sm + S_NBA);
    float* qa   = (float*)(sm + S_QA);
    int*   jv   = (int*)  (sm + S_JV);
    float* Dn   = (float*)(sm + S_DN);
    int*   dpos = (int*)  (sm + S_DP);

    // phase 1: per-edge scalars + query atoms
    if (tid < 128) {
        int r = tid >> 5;
        int brow = row0 + r;
        int j = g_eidx[(size_t)row0*Kv + tid];
        jv[tid] = j;
        Dn[tid] = g_dn[(size_t)row0*Kv + tid];
        int off = ridx[brow] - ridx[(size_t)b*Lv + j];
        int ech = (chl[brow] == chl[(size_t)b*Lv + j]) ? 1 : 0;
        int d = off + 32;
        d = d < 0 ? 0 : (d > 64 ? 64 : d);
        dpos[tid] = ech ? d : 65;
    }
    if (tid >= 160 && tid < 220) {
        int t = tid - 160;
        qa[t] = g_atoms[(size_t)(row0 + t/15)*15 + (t%15)];
    }
    __syncthreads();

    // phase 2: neighbor atom gather
    for (int t = tid; t < 128*15; t += 256) {
        nbA[t] = g_atoms[((size_t)b*Lv + jv[t/15])*15 + (t%15)];
    }
    __syncthreads();

    int e  = tid & 127;
    int s0 = tid >> 7;
    int r  = e >> 5;

    float acc[16][4];
    #pragma unroll
    for (int nt = 0; nt < 16; nt++) {
        acc[nt][0]=0.f; acc[nt][1]=0.f; acc[nt][2]=0.f; acc[nt][3]=0.f;
    }

    unsigned aBaseH = sb + S_AH + (unsigned)(wid*16)*144;
    unsigned aBaseL = sb + S_AL + (unsigned)(wid*16)*144;
    int arow  = lane & 15;
    int acol8 = (lane >> 4) * 8;

    for (int kc = 0; kc < NCH; kc++) {
        // B chunk copy
        {
            const uint4* shi = g_WtHi + kc*CHUNK_U4;
            const uint4* slo = g_WtLo + kc*CHUNK_U4;
            uint4* dhi = (uint4*)(sm + S_BH);
            uint4* dlo = (uint4*)(sm + S_BL);
            for (int i = tid; i < CHUNK_U4; i += 256) {
                dhi[i] = shi[i];
                dlo[i] = slo[i];
            }
        }
        // A chunk build: thread handles edge e, sub-blocks ss = s0, s0+2
        #pragma unroll
        for (int pp = 0; pp < 2; pp++) {
            int ss = s0 + pp*2;
            int S  = kc*4 + ss;
            if (S < 26) {
                float vals[16];
                if (S == 0) {
                    const float4* wp = (const float4*)(Wpos + dpos[e]*16);
                    const float4* bb = (const float4*)bpos;
                    #pragma unroll
                    for (int q = 0; q < 4; q++) {
                        float4 a = wp[q], c = bb[q];
                        vals[q*4+0]=a.x+c.x; vals[q*4+1]=a.y+c.y; vals[q*4+2]=a.z+c.z; vals[q*4+3]=a.w+c.w;
                    }
                } else {
                    float D;
                    if (S == 1) D = Dn[e];
                    else {
                        int p = S - 2;
                        const float* A  = qa  + r*15 + c_PA[p]*3;
                        const float* Bp = nbA + e*15 + c_PB[p]*3;
                        float dx=A[0]-Bp[0], dy=A[1]-Bp[1], dz=A[2]-Bp[2];
                        D = sqrtf(dx*dx + dy*dy + dz*dz + 1e-6f);
                    }
                    #pragma unroll
                    for (int m = 0; m < 16; m++) {
                        float mu = 2.0f + (float)m * (4.0f/3.0f);
                        float z = (D - mu) * 0.8f;
                        vals[m] = __expf(-(z*z));
                    }
                }
                // pack bf16 hi/lo with bf16x2 cvt
                unsigned byteoff = (unsigned)e*144 + (unsigned)ss*32;
                #pragma unroll
                for (int q = 0; q < 2; q++) {
                    unsigned hp[4], lp[4];
                    #pragma unroll
                    for (int j4 = 0; j4 < 4; j4++) {
                        float v0 = vals[q*8 + j4*2], v1 = vals[q*8 + j4*2 + 1];
                        unsigned h = cvt_bf16x2(v1, v0);
                        float h0 = __uint_as_float(h << 16);
                        float h1 = __uint_as_float(h & 0xffff0000u);
                        hp[j4] = h;
                        lp[j4] = cvt_bf16x2(v1 - h1, v0 - h0);
                    }
                    *(uint4*)(sm + S_AH + byteoff + q*16) = make_uint4(hp[0],hp[1],hp[2],hp[3]);
                    *(uint4*)(sm + S_AL + byteoff + q*16) = make_uint4(lp[0],lp[1],lp[2],lp[3]);
                }
            }
        }
        __syncthreads();

        // MMA k-steps (chunk 6: only 2 real k-steps)
        #pragma unroll
        for (int ks = 0; ks < 4; ks++) {
            if (kc == NCH-1 && ks >= 2) break;
            int k0 = ks * 16;
            unsigned ah[4], al[4];
            ldsm4(ah, aBaseH + (unsigned)arow*144 + (unsigned)(k0 + acol8)*2);
            ldsm4(al, aBaseL + (unsigned)arow*144 + (unsigned)(k0 + acol8)*2);
            #pragma unroll
            for (int qg = 0; qg < 4; qg++) {
                unsigned bh0[4], bh1[4], bl0[4], bl1[4];
                unsigned boffH = sb + S_BH + (unsigned)(qg*32 + lane)*144 + (unsigned)k0*2;
                unsigned boffL = sb + S_BL + (unsigned)(qg*32 + lane)*144 + (unsigned)k0*2;
                ldsm4(bh0, boffH);
                ldsm4(bh1, boffH + 16);
                ldsm4(bl0, boffL);
                ldsm4(bl1, boffL + 16);
                #pragma unroll
                for (int m = 0; m < 4; m++) {
                    int nt = qg*4 + m;
                    mma16816(acc[nt], ah, bh0[m], bh1[m]);
                    mma16816(acc[nt], al, bh0[m], bh1[m]);
                    mma16816(acc[nt], ah, bl0[m], bl1[m]);
                }
            }
        }
        __syncthreads();
    }

    // E_idx tail
    if (write_idx && tid < 128) {
        out[(size_t)Bv*Lv*Kv*CD + (size_t)row0*Kv + tid] = (float)jv[tid];
    }

    // epilogue: LayerNorm per edge row. Lane holds cols nt*8+2*(lane&3)+{0,1}
    // for local rows rA = lane>>2 and rB = rA+8.
    {
        int rA = lane >> 2;
        float s1a=0.f, s2a=0.f, s1b=0.f, s2b=0.f;
        #pragma unroll
        for (int nt = 0; nt < 16; nt++) {
            float v0 = acc[nt][0], v1 = acc[nt][1];
            float v2 = acc[nt][2], v3 = acc[nt][3];
            s1a += v0 + v1;  s2a += v0*v0 + v1*v1;
            s1b += v2 + v3;  s2b += v2*v2 + v3*v3;
        }
        #pragma unroll
        for (int o = 1; o <= 2; o <<= 1) {
            s1a += __shfl_xor_sync(0xffffffffu, s1a, o);
            s2a += __shfl_xor_sync(0xffffffffu, s2a, o);
            s1b += __shfl_xor_sync(0xffffffffu, s1b, o);
            s2b += __shfl_xor_sync(0xffffffffu, s2b, o);
        }
        float muA = s1a * (1.0f/128.0f);
        float vrA = s2a * (1.0f/128.0f) - muA*muA;
        float ivA = 1.0f / sqrtf(vrA + 1e-5f);
        float muB = s1b * (1.0f/128.0f);
        float vrB = s2b * (1.0f/128.0f) - muB*muB;
        float ivB = 1.0f / sqrtf(vrB + 1e-5f);

        int eA = wid*16 + rA;
        int eB = eA + 8;
        float* opA = out + ((size_t)row0*Kv + eA) * CD;
        float* opB = out + ((size_t)row0*Kv + eB) * CD;
        int cbase = 2*(lane & 3);
        #pragma unroll
        for (int nt = 0; nt < 16; nt++) {
            int c = nt*8 + cbase;
            float g0 = gamma[c], g1 = gamma[c+1];
            float b0 = beta[c],  b1 = beta[c+1];
            float2 oA, oB;
            oA.x = (acc[nt][0] - muA)*ivA*g0 + b0;
            oA.y = (acc[nt][1] - muA)*ivA*g1 + b1;
            oB.x = (acc[nt][2] - muB)*ivB*g0 + b0;
            oB.y = (acc[nt][3] - muB)*ivB*g1 + b1;
            *(float2*)(opA + c) = oA;
            *(float2*)(opB + c) = oB;
        }
    }
}

// ---------------------------------------------------------------------------
// Launch
// ---------------------------------------------------------------------------
extern "C" void kernel_launch(void* const* d_in, const int* in_sizes, int n_in,
                              void* d_out, int out_size) {
    const float* X     = (const float*)d_in[0];
    const float* mask  = (const float*)d_in[1];
    const int*   ridx  = (const int*)  d_in[2];
    const int*   chl   = (const int*)  d_in[3];
    const float* Wpos  = (const float*)d_in[4];
    const float* bpos  = (const float*)d_in[5];
    const float* Wedge = (const float*)d_in[6];
    const float* gamma = (const float*)d_in[7];
    const float* beta  = (const float*)d_in[8];
    float* out = (float*)d_out;

    const int k2_smem = (Lv*3 + 4*Lv)*4 + 4*256*8;   // 24576+32768+8192 = 65536 B
    cudaFuncSetAttribute(k2_topk, cudaFuncAttributeMaxDynamicSharedMemorySize, k2_smem);
    cudaFuncSetAttribute(k3_mma,  cudaFuncAttributeMaxDynamicSharedMemorySize, S_TOT);

    k0_prepW<<<(KPAD*CD + 255)/256, 256>>>(Wedge);
    k1_atoms<<<(Bv*Lv + 255)/256, 256>>>(X);
    k2_topk<<<Bv*Lv/4, 256, k2_smem>>>(mask);

    long long e_elems = (long long)Bv*Lv*Kv*CD;
    int write_idx = ((long long)out_size >= e_elems + (long long)Bv*Lv*Kv) ? 1 : 0;
    k3_mma<<<GRID3, 256, S_TOT>>>(ridx, chl, Wpos, bpos, gamma, beta, out, write_idx);
}

// round 7
// speedup vs baseline: 4.1727x; 1.1837x over previous
#include <cuda_runtime.h>
#include <cuda_fp16.h>
#include <cstdint>
#include <math.h>

#define Bv 4
#define Lv 2048
#define Kv 32
#define CD 128
#define KPAD 448        // 416 padded to 7*64
#define NCH 7           // K chunks of 64
#define STRD 72         // fp16 elems per row in tiles (144 B, 9x16B -> conflict-free LDSM)
#define CHUNK_U4 1152   // 128 rows * 144 B / 16
#define GRID3 (Bv*Lv/4) // 2048 CTAs, 4 residues (128 edges) each

// Scratch (__device__ globals; no allocation allowed)
__device__ float g_atoms[Bv*Lv*5*3];
__device__ float g_ca[Bv*Lv*3];
__device__ int   g_eidx[Bv*Lv*Kv];
__device__ float g_dn[Bv*Lv*Kv];
__device__ uint4 g_WtHi[NCH*CHUNK_U4];   // W^T fp16 hi, [chunk][n=128][k=64] stride 72
__device__ uint4 g_WtLo[NCH*CHUNK_U4];   // W^T fp16 lo (residual)

__constant__ int c_PA[24] = {0,2,3,4,1,1,1,1,0,0,0,4,4,3,0,2,3,4,2,3,4,2,3,2};
__constant__ int c_PB[24] = {0,2,3,4,0,2,3,4,2,3,4,2,3,2,1,1,1,1,0,0,0,4,4,3};

__device__ __forceinline__ unsigned smem_u32(const void* p) {
    unsigned a;
    asm("{ .reg .u64 t; cvta.to.shared.u64 t, %1; cvt.u32.u64 %0, t; }" : "=r"(a) : "l"(p));
    return a;
}
__device__ __forceinline__ void ldsm4(unsigned* r, unsigned addr) {
    asm volatile("ldmatrix.sync.aligned.m8n8.x4.shared.b16 {%0,%1,%2,%3}, [%4];"
        : "=r"(r[0]), "=r"(r[1]), "=r"(r[2]), "=r"(r[3]) : "r"(addr));
}
__device__ __forceinline__ void mma16816(float* c, const unsigned* a, unsigned b0, unsigned b1) {
    asm volatile("mma.sync.aligned.m16n8k16.row.col.f32.f16.f16.f32 "
        "{%0,%1,%2,%3},{%4,%5,%6,%7},{%8,%9},{%0,%1,%2,%3};"
        : "+f"(c[0]), "+f"(c[1]), "+f"(c[2]), "+f"(c[3])
        : "r"(a[0]), "r"(a[1]), "r"(a[2]), "r"(a[3]), "r"(b0), "r"(b1));
}
__device__ __forceinline__ unsigned long long umin64(unsigned long long a, unsigned long long b) {
    return a < b ? a : b;
}

// ---------------------------------------------------------------------------
// k0: W_edge (416x128 f32) -> fp16 hi/lo tiles: [chunk][n][k], row stride 72
// ---------------------------------------------------------------------------
__global__ void k0_prepW(const float* __restrict__ W) {
    int idx = blockIdx.x * 256 + threadIdx.x;     // KPAD*128 = 57344
    if (idx >= KPAD * CD) return;
    int f = idx >> 7, n = idx & 127;
    float w = (f < 416) ? W[f * CD + n] : 0.0f;
    __half h = __float2half(w);
    __half l = __float2half(w - __half2float(h));
    int kc = f >> 6, kk = f & 63;
    size_t off = (size_t)(kc * 128 + n) * STRD + kk;
    ((__half*)g_WtHi)[off] = h;
    ((__half*)g_WtLo)[off] = l;
}

// ---------------------------------------------------------------------------
// k1: atom table (N, Ca, C, O, Cb)
// ---------------------------------------------------------------------------
__global__ void k1_atoms(const float* __restrict__ X) {
    int i = blockIdx.x * blockDim.x + threadIdx.x;
    if (i >= Bv*Lv) return;
    const float* x = X + (size_t)i * 12;
    float Nx=x[0],Ny=x[1],Nz=x[2];
    float Ax=x[3],Ay=x[4],Az=x[5];
    float Cx=x[6],Cy=x[7],Cz=x[8];
    float Ox=x[9],Oy=x[10],Oz=x[11];
    float bx=Ax-Nx, by=Ay-Ny, bz=Az-Nz;
    float cx=Cx-Ax, cy=Cy-Ay, cz=Cz-Az;
    float ax=by*cz-bz*cy, ay=bz*cx-bx*cz, az=bx*cy-by*cx;
    float Cbx = -0.58273431f*ax + 0.56802827f*bx - 0.54067466f*cx + Ax;
    float Cby = -0.58273431f*ay + 0.56802827f*by - 0.54067466f*cy + Ay;
    float Cbz = -0.58273431f*az + 0.56802827f*bz - 0.54067466f*cz + Az;
    float* p = g_atoms + (size_t)i * 15;
    p[0]=Nx; p[1]=Ny; p[2]=Nz;
    p[3]=Ax; p[4]=Ay; p[5]=Az;
    p[6]=Cx; p[7]=Cy; p[8]=Cz;
    p[9]=Ox; p[10]=Oy; p[11]=Oz;
    p[12]=Cbx; p[13]=Cby; p[14]=Cbz;
    g_ca[i*3+0]=Ax; g_ca[i*3+1]=Ay; g_ca[i*3+2]=Az;
}

// ---------------------------------------------------------------------------
// k2: top-K, 4 rows per 256-thread CTA (proven R6 version).
// ---------------------------------------------------------------------------
__global__ void __launch_bounds__(256)
k2_topk(const float* __restrict__ mask) {
    extern __shared__ char smem_raw[];
    float* ca_s = (float*)smem_raw;                                   // 2048*3 f32 (24KB)
    float* d_s  = ca_s + Lv*3;                                        // 4*2048 f32 (32KB)
    unsigned long long* tmin = (unsigned long long*)(d_s + 4*Lv);     // 4*256 u64 (8KB)
    __shared__ int s_maxi[4];

    int tid  = threadIdx.x;
    int wid  = tid >> 5, lane = tid & 31;
    int row0 = blockIdx.x * 4;
    int b    = row0 >> 11;

    if (tid < 4) s_maxi[tid] = 0;
    const float* cab = g_ca + (size_t)b * Lv * 3;
    for (int i = tid; i < Lv*3; i += 256) ca_s[i] = cab[i];
    __syncthreads();

    float cx[4], cy[4], cz[4], mi[4];
    #pragma unroll
    for (int r = 0; r < 4; r++) {
        int li = (row0 + r) & (Lv-1);
        cx[r] = ca_s[li*3+0]; cy[r] = ca_s[li*3+1]; cz[r] = ca_s[li*3+2];
        mi[r] = mask[(size_t)row0 + r];
    }
    const float* mb = mask + (size_t)b * Lv;

    int j0 = tid * 8;
    float Dreg[4][8], mbj[8];
    float lmax[4] = {0.f, 0.f, 0.f, 0.f};
    #pragma unroll
    for (int s = 0; s < 8; s++) {
        int j = j0 + s;
        float px = ca_s[j*3+0], py = ca_s[j*3+1], pz = ca_s[j*3+2];
        mbj[s] = mb[j];
        #pragma unroll
        for (int r = 0; r < 4; r++) {
            float dx = cx[r]-px, dy = cy[r]-py, dz = cz[r]-pz;
            float d  = sqrtf(dx*dx + dy*dy + dz*dz + 1e-6f);
            float D  = mi[r] * mbj[s] * d;
            Dreg[r][s] = D;
            lmax[r] = fmaxf(lmax[r], D);
        }
    }
    #pragma unroll
    for (int r = 0; r < 4; r++) {
        float v = lmax[r];
        #pragma unroll
        for (int o = 16; o; o >>= 1) v = fmaxf(v, __shfl_xor_sync(0xffffffffu, v, o));
        if (lane == 0) atomicMax(&s_maxi[r], __float_as_int(v));
    }
    __syncthreads();

    #pragma unroll
    for (int r = 0; r < 4; r++) {
        float Dmax = __int_as_float(s_maxi[r]);
        unsigned long long mn = ~0ULL;
        #pragma unroll
        for (int s = 0; s < 8; s++) {
            int j = j0 + s;
            float m2 = mi[r] * mbj[s];
            float Dadj = Dreg[r][s] + (1.0f - m2) * Dmax;
            d_s[r*Lv + j] = Dadj;
            unsigned long long k = (((unsigned long long)__float_as_uint(Dadj)) << 32) | (unsigned)j;
            mn = umin64(mn, k);
        }
        tmin[r*256 + tid] = mn;
    }
    __syncthreads();

    if (wid < 4) {
        int r = wid;
        int row = row0 + r;
        float* dr = d_s + r*Lv;
        unsigned long long m[8];
        #pragma unroll
        for (int s = 0; s < 8; s++) m[s] = tmin[r*256 + lane*8 + s];

        for (int rnd = 0; rnd < Kv; rnd++) {
            unsigned long long w = m[0];
            #pragma unroll
            for (int s = 1; s < 8; s++) w = umin64(w, m[s]);
            #pragma unroll
            for (int o = 16; o; o >>= 1) {
                unsigned long long v = __shfl_xor_sync(0xffffffffu, w, o);
                w = umin64(w, v);
            }
            int j = (int)(unsigned)(w & 0xffffffffu);
            if (lane == 0) {
                g_eidx[(size_t)row*Kv + rnd] = j;
                g_dn[(size_t)row*Kv + rnd]   = __uint_as_float((unsigned)(w >> 32));
            }
            int t = j >> 3;
            if ((t >> 3) == lane) {
                dr[j] = __int_as_float(0x7f800000);
                unsigned long long nm = ~0ULL;
                #pragma unroll
                for (int s = 0; s < 8; s++) {
                    int jj = t*8 + s;
                    float Dv = dr[jj];
                    unsigned long long k = (((unsigned long long)__float_as_uint(Dv)) << 32) | (unsigned)jj;
                    nm = umin64(nm, k);
                }
                m[t & 7] = nm;
            }
        }
    }
}

// ---------------------------------------------------------------------------
// k3: fused feature-build + mma.sync fp16 GEMM + LayerNorm.
// CTA = 4 residues x 32 nbrs = 128 edges. Warp w owns edge rows 16w..16w+15.
// A single fp16 (error 2^-11 per term); W split fp16 hi/lo -> 2 passes:
// C = A*Wh + A*Wl. Chunk 6: only 2 real k-steps.
// ---------------------------------------------------------------------------
#define S_A   0
#define S_BH  18432
#define S_BL  36864
#define S_NBA 55296                       // 128*15 f32 = 7680
#define S_QA  (S_NBA + 7680)              // 60 f32
#define S_JV  (S_QA + 240)                // 128 int
#define S_DN  (S_JV + 512)                // 128 f32
#define S_DP  (S_DN + 512)                // 128 int
#define S_TOT (S_DP + 512)                // 64752 B

__global__ void __launch_bounds__(256)
k3_mma(const int* __restrict__ ridx, const int* __restrict__ chl,
       const float* __restrict__ Wpos, const float* __restrict__ bpos,
       const float* __restrict__ gamma, const float* __restrict__ beta,
       float* __restrict__ out, int write_idx) {
    extern __shared__ unsigned char sm[];
    unsigned sb = smem_u32(sm);
    int tid  = threadIdx.x;
    int wid  = tid >> 5, lane = tid & 31;
    int row0 = blockIdx.x * 4;
    int b    = row0 >> 11;

    float* nbA  = (float*)(sm + S_NBA);
    float* qa   = (float*)(sm + S_QA);
    int*   jv   = (int*)  (sm + S_JV);
    float* Dn   = (float*)(sm + S_DN);
    int*   dpos = (int*)  (sm + S_DP);

    // phase 1: per-edge scalars + query atoms
    if (tid < 128) {
        int r = tid >> 5;
        int brow = row0 + r;
        int j = g_eidx[(size_t)row0*Kv + tid];
        jv[tid] = j;
        Dn[tid] = g_dn[(size_t)row0*Kv + tid];
        int off = ridx[brow] - ridx[(size_t)b*Lv + j];
        int ech = (chl[brow] == chl[(size_t)b*Lv + j]) ? 1 : 0;
        int d = off + 32;
        d = d < 0 ? 0 : (d > 64 ? 64 : d);
        dpos[tid] = ech ? d : 65;
    }
    if (tid >= 160 && tid < 220) {
        int t = tid - 160;
        qa[t] = g_atoms[(size_t)(row0 + t/15)*15 + (t%15)];
    }
    __syncthreads();

    // phase 2: neighbor atom gather
    for (int t = tid; t < 128*15; t += 256) {
        nbA[t] = g_atoms[((size_t)b*Lv + jv[t/15])*15 + (t%15)];
    }
    __syncthreads();

    int e  = tid & 127;
    int s0 = tid >> 7;
    int r  = e >> 5;

    float acc[16][4];
    #pragma unroll
    for (int nt = 0; nt < 16; nt++) {
        acc[nt][0]=0.f; acc[nt][1]=0.f; acc[nt][2]=0.f; acc[nt][3]=0.f;
    }

    unsigned aBase = sb + S_A + (unsigned)(wid*16)*144;
    int arow  = lane & 15;
    int acol8 = (lane >> 4) * 8;

    for (int kc = 0; kc < NCH; kc++) {
        // B chunk copy (hi + lo)
        {
            const uint4* shi = g_WtHi + kc*CHUNK_U4;
            const uint4* slo = g_WtLo + kc*CHUNK_U4;
            uint4* dhi = (uint4*)(sm + S_BH);
            uint4* dlo = (uint4*)(sm + S_BL);
            for (int i = tid; i < CHUNK_U4; i += 256) {
                dhi[i] = shi[i];
                dlo[i] = slo[i];
            }
        }
        // A chunk build: thread handles edge e, sub-blocks ss = s0, s0+2
        #pragma unroll
        for (int pp = 0; pp < 2; pp++) {
            int ss = s0 + pp*2;
            int S  = kc*4 + ss;
            if (S < 26) {
                float vals[16];
                if (S == 0) {
                    const float4* wp = (const float4*)(Wpos + dpos[e]*16);
                    const float4* bb = (const float4*)bpos;
                    #pragma unroll
                    for (int q = 0; q < 4; q++) {
                        float4 a = wp[q], c = bb[q];
                        vals[q*4+0]=a.x+c.x; vals[q*4+1]=a.y+c.y; vals[q*4+2]=a.z+c.z; vals[q*4+3]=a.w+c.w;
                    }
                } else {
                    float D;
                    if (S == 1) D = Dn[e];
                    else {
                        int p = S - 2;
                        const float* A  = qa  + r*15 + c_PA[p]*3;
                        const float* Bp = nbA + e*15 + c_PB[p]*3;
                        float dx=A[0]-Bp[0], dy=A[1]-Bp[1], dz=A[2]-Bp[2];
                        D = sqrtf(dx*dx + dy*dy + dz*dz + 1e-6f);
                    }
                    #pragma unroll
                    for (int m = 0; m < 16; m++) {
                        float mu = 2.0f + (float)m * (4.0f/3.0f);
                        float z = (D - mu) * 0.8f;
                        vals[m] = __expf(-(z*z));
                    }
                }
                unsigned byteoff = (unsigned)e*144 + (unsigned)ss*32;
                #pragma unroll
                for (int q = 0; q < 2; q++) {
                    unsigned hp[4];
                    #pragma unroll
                    for (int j4 = 0; j4 < 4; j4++) {
                        __half2 h2 = __floats2half2_rn(vals[q*8 + j4*2], vals[q*8 + j4*2 + 1]);
                        hp[j4] = *(unsigned*)&h2;
                    }
                    *(uint4*)(sm + S_A + byteoff + q*16) = make_uint4(hp[0],hp[1],hp[2],hp[3]);
                }
            }
        }
        __syncthreads();

        // MMA k-steps (chunk 6: only 2 real k-steps); 2 passes: A*Bh + A*Bl
        #pragma unroll
        for (int ks = 0; ks < 4; ks++) {
            if (kc == NCH-1 && ks >= 2) break;
            int k0 = ks * 16;
            unsigned av[4];
            ldsm4(av, aBase + (unsigned)arow*144 + (unsigned)(k0 + acol8)*2);
            #pragma unroll
            for (int qg = 0; qg < 4; qg++) {
                unsigned bh0[4], bh1[4], bl0[4], bl1[4];
                unsigned boffH = sb + S_BH + (unsigned)(qg*32 + lane)*144 + (unsigned)k0*2;
                unsigned boffL = sb + S_BL + (unsigned)(qg*32 + lane)*144 + (unsigned)k0*2;
                ldsm4(bh0, boffH);
                ldsm4(bh1, boffH + 16);
                ldsm4(bl0, boffL);
                ldsm4(bl1, boffL + 16);
                #pragma unroll
                for (int m = 0; m < 4; m++) {
                    int nt = qg*4 + m;
                    mma16816(acc[nt], av, bh0[m], bh1[m]);
                    mma16816(acc[nt], av, bl0[m], bl1[m]);
                }
            }
        }
        __syncthreads();
    }

    // E_idx tail
    if (write_idx && tid < 128) {
        out[(size_t)Bv*Lv*Kv*CD + (size_t)row0*Kv + tid] = (float)jv[tid];
    }

    // epilogue: LayerNorm per edge row
    {
        int rA = lane >> 2;
        float s1a=0.f, s2a=0.f, s1b=0.f, s2b=0.f;
        #pragma unroll
        for (int nt = 0; nt < 16; nt++) {
            float v0 = acc[nt][0], v1 = acc[nt][1];
            float v2 = acc[nt][2], v3 = acc[nt][3];
            s1a += v0 + v1;  s2a += v0*v0 + v1*v1;
            s1b += v2 + v3;  s2b += v2*v2 + v3*v3;
        }
        #pragma unroll
        for (int o = 1; o <= 2; o <<= 1) {
            s1a += __shfl_xor_sync(0xffffffffu, s1a, o);
            s2a += __shfl_xor_sync(0xffffffffu, s2a, o);
            s1b += __shfl_xor_sync(0xffffffffu, s1b, o);
            s2b += __shfl_xor_sync(0xffffffffu, s2b, o);
        }
        float muA = s1a * (1.0f/128.0f);
        float vrA = s2a * (1.0f/128.0f) - muA*muA;
        float ivA = 1.0f / sqrtf(vrA + 1e-5f);
        float muB = s1b * (1.0f/128.0f);
        float vrB = s2b * (1.0f/128.0f) - muB*muB;
        float ivB = 1.0f / sqrtf(vrB + 1e-5f);

        int eA = wid*16 + rA;
        int eB = eA + 8;
        float* opA = out + ((size_t)row0*Kv + eA) * CD;
        float* opB = out + ((size_t)row0*Kv + eB) * CD;
        int cbase = 2*(lane & 3);
        #pragma unroll
        for (int nt = 0; nt < 16; nt++) {
            int c = nt*8 + cbase;
            float g0 = gamma[c], g1 = gamma[c+1];
            float b0 = beta[c],  b1 = beta[c+1];
            float2 oA, oB;
            oA.x = (acc[nt][0] - muA)*ivA*g0 + b0;
            oA.y = (acc[nt][1] - muA)*ivA*g1 + b1;
            oB.x = (acc[nt][2] - muB)*ivB*g0 + b0;
            oB.y = (acc[nt][3] - muB)*ivB*g1 + b1;
            *(float2*)(opA + c) = oA;
            *(float2*)(opB + c) = oB;
        }
    }
}

// ---------------------------------------------------------------------------
// Launch
// ---------------------------------------------------------------------------
extern "C" void kernel_launch(void* const* d_in, const int* in_sizes, int n_in,
                              void* d_out, int out_size) {
    const float* X     = (const float*)d_in[0];
    const float* mask  = (const float*)d_in[1];
    const int*   ridx  = (const int*)  d_in[2];
    const int*   chl   = (const int*)  d_in[3];
    const float* Wpos  = (const float*)d_in[4];
    const float* bpos  = (const float*)d_in[5];
    const float* Wedge = (const float*)d_in[6];
    const float* gamma = (const float*)d_in[7];
    const float* beta  = (const float*)d_in[8];
    float* out = (float*)d_out;

    const int k2_smem = (Lv*3 + 4*Lv)*4 + 4*256*8;   // 65536 B
    cudaFuncSetAttribute(k2_topk, cudaFuncAttributeMaxDynamicSharedMemorySize, k2_smem);
    cudaFuncSetAttribute(k3_mma,  cudaFuncAttributeMaxDynamicSharedMemorySize, S_TOT);

    k0_prepW<<<(KPAD*CD + 255)/256, 256>>>(Wedge);
    k1_atoms<<<(Bv*Lv + 255)/256, 256>>>(X);
    k2_topk<<<Bv*Lv/4, 256, k2_smem>>>(mask);

    long long e_elems = (long long)Bv*Lv*Kv*CD;
    int write_idx = ((long long)out_size >= e_elems + (long long)Bv*Lv*Kv) ? 1 : 0;
    k3_mma<<<GRID3, 256, S_TOT>>>(ridx, chl, Wpos, bpos, gamma, beta, out, write_idx);
}

// round 8
// speedup vs baseline: 4.5994x; 1.1023x over previous
#include <cuda_runtime.h>
#include <cuda_fp16.h>
#include <cstdint>
#include <math.h>

#define Bv 4
#define Lv 2048
#define Kv 32
#define CD 128
#define KPAD 448        // 416 padded to 7*64
#define NCH 7           // K chunks of 64
#define NKSG 28         // total k-steps of 16 (26 real)
#define GRID3 (Bv*Lv/4) // 2048 CTAs, 4 residues (128 edges) each

// Scratch (__device__ globals; no allocation allowed)
__device__ float g_atoms[Bv*Lv*5*3];
__device__ float g_ca[Bv*Lv*3];
__device__ int   g_eidx[Bv*Lv*Kv];
__device__ float g_dn[Bv*Lv*Kv];
// W in mma b-fragment layout: [ksg(28)][nt(16)][pass(2)][lane(32)] -> uint2 {b0,b1}
__device__ uint2 g_Wf[NKSG*16*2*32];

__constant__ int c_PA[24] = {0,2,3,4,1,1,1,1,0,0,0,4,4,3,0,2,3,4,2,3,4,2,3,2};
__constant__ int c_PB[24] = {0,2,3,4,0,2,3,4,2,3,4,2,3,2,1,1,1,1,0,0,0,4,4,3};

__device__ __forceinline__ unsigned smem_u32(const void* p) {
    unsigned a;
    asm("{ .reg .u64 t; cvta.to.shared.u64 t, %1; cvt.u32.u64 %0, t; }" : "=r"(a) : "l"(p));
    return a;
}
__device__ __forceinline__ void ldsm4(unsigned* r, unsigned addr) {
    asm volatile("ldmatrix.sync.aligned.m8n8.x4.shared.b16 {%0,%1,%2,%3}, [%4];"
        : "=r"(r[0]), "=r"(r[1]), "=r"(r[2]), "=r"(r[3]) : "r"(addr));
}
__device__ __forceinline__ void mma16816(float* c, const unsigned* a, unsigned b0, unsigned b1) {
    asm volatile("mma.sync.aligned.m16n8k16.row.col.f32.f16.f16.f32 "
        "{%0,%1,%2,%3},{%4,%5,%6,%7},{%8,%9},{%0,%1,%2,%3};"
        : "+f"(c[0]), "+f"(c[1]), "+f"(c[2]), "+f"(c[3])
        : "r"(a[0]), "r"(a[1]), "r"(a[2]), "r"(a[3]), "r"(b0), "r"(b1));
}
__device__ __forceinline__ unsigned long long umin64(unsigned long long a, unsigned long long b) {
    return a < b ? a : b;
}

// ---------------------------------------------------------------------------
// k0: W_edge (416x128 f32) -> fp16 hi/lo fragments in mma b-frag layout.
// For m16n8k16 row.col: lane holds b0 = (k0, n),(k0+1, n); b1 = (k0+8..9, n)
// with k0 = (lane&3)*2, n = lane>>2 within the 16(k)x8(n) tile.
// ---------------------------------------------------------------------------
__global__ void k0_prepW(const float* __restrict__ W) {
    int idx = blockIdx.x * 256 + threadIdx.x;     // NKSG*16*2*32 = 28672
    if (idx >= NKSG*16*2*32) return;
    int lane = idx & 31;
    int pass = (idx >> 5) & 1;
    int nt   = (idx >> 6) & 15;
    int ksg  = idx >> 10;
    int n  = nt*8 + (lane >> 2);
    int k0 = ksg*16 + (lane & 3)*2;
    float w[4];
    #pragma unroll
    for (int q = 0; q < 4; q++) {
        int f = k0 + (q >> 1)*8 + (q & 1);
        w[q] = (f < 416) ? W[f * CD + n] : 0.0f;
    }
    unsigned r[2];
    #pragma unroll
    for (int h = 0; h < 2; h++) {
        float v0 = w[h*2], v1 = w[h*2+1];
        __half h0 = __float2half(v0), h1 = __float2half(v1);
        if (pass == 1) {  // lo residual
            h0 = __float2half(v0 - __half2float(h0));
            h1 = __float2half(v1 - __half2float(h1));
        }
        __half2 p = __halves2half2(h0, h1);
        r[h] = *(unsigned*)&p;
    }
    g_Wf[idx] = make_uint2(r[0], r[1]);
}

// ---------------------------------------------------------------------------
// k1: atom table (N, Ca, C, O, Cb)
// ---------------------------------------------------------------------------
__global__ void k1_atoms(const float* __restrict__ X) {
    int i = blockIdx.x * blockDim.x + threadIdx.x;
    if (i >= Bv*Lv) return;
    const float* x = X + (size_t)i * 12;
    float Nx=x[0],Ny=x[1],Nz=x[2];
    float Ax=x[3],Ay=x[4],Az=x[5];
    float Cx=x[6],Cy=x[7],Cz=x[8];
    float Ox=x[9],Oy=x[10],Oz=x[11];
    float bx=Ax-Nx, by=Ay-Ny, bz=Az-Nz;
    float cx=Cx-Ax, cy=Cy-Ay, cz=Cz-Az;
    float ax=by*cz-bz*cy, ay=bz*cx-bx*cz, az=bx*cy-by*cx;
    float Cbx = -0.58273431f*ax + 0.56802827f*bx - 0.54067466f*cx + Ax;
    float Cby = -0.58273431f*ay + 0.56802827f*by - 0.54067466f*cy + Ay;
    float Cbz = -0.58273431f*az + 0.56802827f*bz - 0.54067466f*cz + Az;
    float* p = g_atoms + (size_t)i * 15;
    p[0]=Nx; p[1]=Ny; p[2]=Nz;
    p[3]=Ax; p[4]=Ay; p[5]=Az;
    p[6]=Cx; p[7]=Cy; p[8]=Cz;
    p[9]=Ox; p[10]=Oy; p[11]=Oz;
    p[12]=Cbx; p[13]=Cby; p[14]=Cbz;
    g_ca[i*3+0]=Ax; g_ca[i*3+1]=Ay; g_ca[i*3+2]=Az;
}

// ---------------------------------------------------------------------------
// k2: top-K, 4 rows per 256-thread CTA (proven R6 version).
// ---------------------------------------------------------------------------
__global__ void __launch_bounds__(256)
k2_topk(const float* __restrict__ mask) {
    extern __shared__ char smem_raw[];
    float* ca_s = (float*)smem_raw;
    float* d_s  = ca_s + Lv*3;
    unsigned long long* tmin = (unsigned long long*)(d_s + 4*Lv);
    __shared__ int s_maxi[4];

    int tid  = threadIdx.x;
    int wid  = tid >> 5, lane = tid & 31;
    int row0 = blockIdx.x * 4;
    int b    = row0 >> 11;

    if (tid < 4) s_maxi[tid] = 0;
    const float* cab = g_ca + (size_t)b * Lv * 3;
    for (int i = tid; i < Lv*3; i += 256) ca_s[i] = cab[i];
    __syncthreads();

    float cx[4], cy[4], cz[4], mi[4];
    #pragma unroll
    for (int r = 0; r < 4; r++) {
        int li = (row0 + r) & (Lv-1);
        cx[r] = ca_s[li*3+0]; cy[r] = ca_s[li*3+1]; cz[r] = ca_s[li*3+2];
        mi[r] = mask[(size_t)row0 + r];
    }
    const float* mb = mask + (size_t)b * Lv;

    int j0 = tid * 8;
    float Dreg[4][8], mbj[8];
    float lmax[4] = {0.f, 0.f, 0.f, 0.f};
    #pragma unroll
    for (int s = 0; s < 8; s++) {
        int j = j0 + s;
        float px = ca_s[j*3+0], py = ca_s[j*3+1], pz = ca_s[j*3+2];
        mbj[s] = mb[j];
        #pragma unroll
        for (int r = 0; r < 4; r++) {
            float dx = cx[r]-px, dy = cy[r]-py, dz = cz[r]-pz;
            float d  = sqrtf(dx*dx + dy*dy + dz*dz + 1e-6f);
            float D  = mi[r] * mbj[s] * d;
            Dreg[r][s] = D;
            lmax[r] = fmaxf(lmax[r], D);
        }
    }
    #pragma unroll
    for (int r = 0; r < 4; r++) {
        float v = lmax[r];
        #pragma unroll
        for (int o = 16; o; o >>= 1) v = fmaxf(v, __shfl_xor_sync(0xffffffffu, v, o));
        if (lane == 0) atomicMax(&s_maxi[r], __float_as_int(v));
    }
    __syncthreads();

    #pragma unroll
    for (int r = 0; r < 4; r++) {
        float Dmax = __int_as_float(s_maxi[r]);
        unsigned long long mn = ~0ULL;
        #pragma unroll
        for (int s = 0; s < 8; s++) {
            int j = j0 + s;
            float m2 = mi[r] * mbj[s];
            float Dadj = Dreg[r][s] + (1.0f - m2) * Dmax;
            d_s[r*Lv + j] = Dadj;
            unsigned long long k = (((unsigned long long)__float_as_uint(Dadj)) << 32) | (unsigned)j;
            mn = umin64(mn, k);
        }
        tmin[r*256 + tid] = mn;
    }
    __syncthreads();

    if (wid < 4) {
        int r = wid;
        int row = row0 + r;
        float* dr = d_s + r*Lv;
        unsigned long long m[8];
        #pragma unroll
        for (int s = 0; s < 8; s++) m[s] = tmin[r*256 + lane*8 + s];

        for (int rnd = 0; rnd < Kv; rnd++) {
            unsigned long long w = m[0];
            #pragma unroll
            for (int s = 1; s < 8; s++) w = umin64(w, m[s]);
            #pragma unroll
            for (int o = 16; o; o >>= 1) {
                unsigned long long v = __shfl_xor_sync(0xffffffffu, w, o);
                w = umin64(w, v);
            }
            int j = (int)(unsigned)(w & 0xffffffffu);
            if (lane == 0) {
                g_eidx[(size_t)row*Kv + rnd] = j;
                g_dn[(size_t)row*Kv + rnd]   = __uint_as_float((unsigned)(w >> 32));
            }
            int t = j >> 3;
            if ((t >> 3) == lane) {
                dr[j] = __int_as_float(0x7f800000);
                unsigned long long nm = ~0ULL;
                #pragma unroll
                for (int s = 0; s < 8; s++) {
                    int jj = t*8 + s;
                    float Dv = dr[jj];
                    unsigned long long k = (((unsigned long long)__float_as_uint(Dv)) << 32) | (unsigned)jj;
                    nm = umin64(nm, k);
                }
                m[t & 7] = nm;
            }
        }
    }
}

// ---------------------------------------------------------------------------
// k3: fused feature-build + fp16 mma GEMM (2-pass W hi/lo) + LayerNorm.
// CTA = 128 edges. Warp w owns n-cols [16w,16w+16) for ALL 128 edge rows:
// B fragments come straight from g_Wf (global, L2-hot) -> no B smem at all.
// A (features) built in smem per 64-wide chunk, read via ldmatrix.
// LayerNorm uses cross-warp smem atomic reduction.
// ---------------------------------------------------------------------------
#define S_A   0                           // 128*144 = 18432
#define S_NBA 18432                       // 128*15 f32 = 7680
#define S_QA  (S_NBA + 7680)              // 60 f32 -> 240
#define S_JV  (S_QA + 240)                // 128 int
#define S_DN  (S_JV + 512)                // 128 f32
#define S_DP  (S_DN + 512)                // 128 int
#define S_S1  (S_DP + 512)                // 128 f32 LN sum
#define S_S2  (S_S1 + 512)                // 128 f32 LN sumsq
#define S_TOT (S_S2 + 512)                // 28912 B

__global__ void __launch_bounds__(256)
k3_mma(const int* __restrict__ ridx, const int* __restrict__ chl,
       const float* __restrict__ Wpos, const float* __restrict__ bpos,
       const float* __restrict__ gamma, const float* __restrict__ beta,
       float* __restrict__ out, int write_idx) {
    extern __shared__ unsigned char sm[];
    unsigned sb = smem_u32(sm);
    int tid  = threadIdx.x;
    int wid  = tid >> 5, lane = tid & 31;
    int row0 = blockIdx.x * 4;
    int b    = row0 >> 11;

    float* nbA  = (float*)(sm + S_NBA);
    float* qa   = (float*)(sm + S_QA);
    int*   jv   = (int*)  (sm + S_JV);
    float* Dn   = (float*)(sm + S_DN);
    int*   dpos = (int*)  (sm + S_DP);
    float* s_s1 = (float*)(sm + S_S1);
    float* s_s2 = (float*)(sm + S_S2);

    // phase 1: per-edge scalars + query atoms + LN accumulators
    if (tid < 128) {
        int r = tid >> 5;
        int brow = row0 + r;
        int j = g_eidx[(size_t)row0*Kv + tid];
        jv[tid] = j;
        Dn[tid] = g_dn[(size_t)row0*Kv + tid];
        int off = ridx[brow] - ridx[(size_t)b*Lv + j];
        int ech = (chl[brow] == chl[(size_t)b*Lv + j]) ? 1 : 0;
        int d = off + 32;
        d = d < 0 ? 0 : (d > 64 ? 64 : d);
        dpos[tid] = ech ? d : 65;
        s_s1[tid] = 0.0f;
        s_s2[tid] = 0.0f;
    }
    if (tid >= 160 && tid < 220) {
        int t = tid - 160;
        qa[t] = g_atoms[(size_t)(row0 + t/15)*15 + (t%15)];
    }
    __syncthreads();

    // phase 2: neighbor atom gather
    for (int t = tid; t < 128*15; t += 256) {
        nbA[t] = g_atoms[((size_t)b*Lv + jv[t/15])*15 + (t%15)];
    }
    __syncthreads();

    int e  = tid & 127;
    int s0 = tid >> 7;
    int r  = e >> 5;

    // acc[mt][nt2][4]: mt = m-tile (16 rows), nt2 = n-tile within warp slice
    float acc[8][2][4];
    #pragma unroll
    for (int mt = 0; mt < 8; mt++)
        #pragma unroll
        for (int n2 = 0; n2 < 2; n2++) {
            acc[mt][n2][0]=0.f; acc[mt][n2][1]=0.f; acc[mt][n2][2]=0.f; acc[mt][n2][3]=0.f;
        }

    int arow  = lane & 15;
    int acol8 = (lane >> 4) * 8;
    const uint2* __restrict__ Wf = g_Wf;

    for (int kc = 0; kc < NCH; kc++) {
        // A chunk build: thread handles edge e, sub-blocks ss = s0, s0+2
        #pragma unroll
        for (int pp = 0; pp < 2; pp++) {
            int ss = s0 + pp*2;
            int S  = kc*4 + ss;
            if (S < 26) {
                float vals[16];
                if (S == 0) {
                    const float4* wp = (const float4*)(Wpos + dpos[e]*16);
                    const float4* bb = (const float4*)bpos;
                    #pragma unroll
                    for (int q = 0; q < 4; q++) {
                        float4 a = wp[q], c = bb[q];
                        vals[q*4+0]=a.x+c.x; vals[q*4+1]=a.y+c.y; vals[q*4+2]=a.z+c.z; vals[q*4+3]=a.w+c.w;
                    }
                } else {
                    float D;
                    if (S == 1) D = Dn[e];
                    else {
                        int p = S - 2;
                        const float* A  = qa  + r*15 + c_PA[p]*3;
                        const float* Bp = nbA + e*15 + c_PB[p]*3;
                        float dx=A[0]-Bp[0], dy=A[1]-Bp[1], dz=A[2]-Bp[2];
                        D = sqrtf(dx*dx + dy*dy + dz*dz + 1e-6f);
                    }
                    #pragma unroll
                    for (int m = 0; m < 16; m++) {
                        float mu = 2.0f + (float)m * (4.0f/3.0f);
                        float z = (D - mu) * 0.8f;
                        vals[m] = __expf(-(z*z));
                    }
                }
                unsigned byteoff = (unsigned)e*144 + (unsigned)ss*32;
                #pragma unroll
                for (int q = 0; q < 2; q++) {
                    unsigned hp[4];
                    #pragma unroll
                    for (int j4 = 0; j4 < 4; j4++) {
                        __half2 h2 = __floats2half2_rn(vals[q*8 + j4*2], vals[q*8 + j4*2 + 1]);
                        hp[j4] = *(unsigned*)&h2;
                    }
                    *(uint4*)(sm + S_A + byteoff + q*16) = make_uint4(hp[0],hp[1],hp[2],hp[3]);
                }
            }
        }
        __syncthreads();

        int nks = (kc == NCH-1) ? 2 : 4;
        for (int ks = 0; ks < nks; ks++) {
            int ksg = kc*4 + ks;
            int k0  = ks * 16;
            // B fragments from global (L2-hot), this warp's 2 n-tiles x 2 passes
            uint2 bf[2][2];
            #pragma unroll
            for (int n2 = 0; n2 < 2; n2++)
                #pragma unroll
                for (int ps = 0; ps < 2; ps++)
                    bf[n2][ps] = Wf[(((ksg*16) + (wid*2 + n2))*2 + ps)*32 + lane];
            // A fragments in two halves of 4 m-tiles (register pressure)
            #pragma unroll
            for (int half = 0; half < 2; half++) {
                unsigned a[4][4];
                #pragma unroll
                for (int q = 0; q < 4; q++) {
                    int mt = half*4 + q;
                    ldsm4(a[q], sb + S_A + (unsigned)(mt*16 + arow)*144 + (unsigned)(k0 + acol8)*2);
                }
                #pragma unroll
                for (int q = 0; q < 4; q++) {
                    int mt = half*4 + q;
                    #pragma unroll
                    for (int n2 = 0; n2 < 2; n2++) {
                        mma16816(acc[mt][n2], a[q], bf[n2][0].x, bf[n2][0].y);
                        mma16816(acc[mt][n2], a[q], bf[n2][1].x, bf[n2][1].y);
                    }
                }
            }
        }
        __syncthreads();
    }

    // E_idx tail
    if (write_idx && tid < 128) {
        out[(size_t)Bv*Lv*Kv*CD + (size_t)row0*Kv + tid] = (float)jv[tid];
    }

    // LayerNorm partials: reduce this warp's 16 cols per row, atomicAdd to smem
    #pragma unroll
    for (int mt = 0; mt < 8; mt++) {
        float pA1 = acc[mt][0][0] + acc[mt][0][1] + acc[mt][1][0] + acc[mt][1][1];
        float pA2 = acc[mt][0][0]*acc[mt][0][0] + acc[mt][0][1]*acc[mt][0][1]
                  + acc[mt][1][0]*acc[mt][1][0] + acc[mt][1][1]*acc[mt][1][1];
        float pB1 = acc[mt][0][2] + acc[mt][0][3] + acc[mt][1][2] + acc[mt][1][3];
        float pB2 = acc[mt][0][2]*acc[mt][0][2] + acc[mt][0][3]*acc[mt][0][3]
                  + acc[mt][1][2]*acc[mt][1][2] + acc[mt][1][3]*acc[mt][1][3];
        #pragma unroll
        for (int o = 1; o <= 2; o <<= 1) {
            pA1 += __shfl_xor_sync(0xffffffffu, pA1, o);
            pA2 += __shfl_xor_sync(0xffffffffu, pA2, o);
            pB1 += __shfl_xor_sync(0xffffffffu, pB1, o);
            pB2 += __shfl_xor_sync(0xffffffffu, pB2, o);
        }
        if ((lane & 3) == 0) {
            int rA = mt*16 + (lane >> 2);
            atomicAdd(&s_s1[rA],     pA1);
            atomicAdd(&s_s2[rA],     pA2);
            atomicAdd(&s_s1[rA + 8], pB1);
            atomicAdd(&s_s2[rA + 8], pB2);
        }
    }
    __syncthreads();

    // normalize + write: this warp's 16-col slice for all 128 rows
    {
        int cb = wid*16 + 2*(lane & 3);
        float g0a = gamma[cb],     g1a = gamma[cb+1];
        float b0a = beta[cb],      b1a = beta[cb+1];
        float g0b = gamma[cb+8],   g1b = gamma[cb+9];
        float b0b = beta[cb+8],    b1b = beta[cb+9];
        #pragma unroll
        for (int mt = 0; mt < 8; mt++) {
            int rA = mt*16 + (lane >> 2);
            int rB = rA + 8;
            float muA = s_s1[rA] * (1.0f/128.0f);
            float vrA = s_s2[rA] * (1.0f/128.0f) - muA*muA;
            float ivA = 1.0f / sqrtf(vrA + 1e-5f);
            float muB = s_s1[rB] * (1.0f/128.0f);
            float vrB = s_s2[rB] * (1.0f/128.0f) - muB*muB;
            float ivB = 1.0f / sqrtf(vrB + 1e-5f);
            float* opA = out + ((size_t)row0*Kv + rA) * CD;
            float* opB = out + ((size_t)row0*Kv + rB) * CD;
            float2 oA0, oA1, oB0, oB1;
            oA0.x = (acc[mt][0][0] - muA)*ivA*g0a + b0a;
            oA0.y = (acc[mt][0][1] - muA)*ivA*g1a + b1a;
            oA1.x = (acc[mt][1][0] - muA)*ivA*g0b + b0b;
            oA1.y = (acc[mt][1][1] - muA)*ivA*g1b + b1b;
            oB0.x = (acc[mt][0][2] - muB)*ivB*g0a + b0a;
            oB0.y = (acc[mt][0][3] - muB)*ivB*g1a + b1a;
            oB1.x = (acc[mt][1][2] - muB)*ivB*g0b + b0b;
            oB1.y = (acc[mt][1][3] - muB)*ivB*g1b + b1b;
            *(float2*)(opA + cb)     = oA0;
            *(float2*)(opA + cb + 8) = oA1;
            *(float2*)(opB + cb)     = oB0;
            *(float2*)(opB + cb + 8) = oB1;
        }
    }
}

// ---------------------------------------------------------------------------
// Launch
// ---------------------------------------------------------------------------
extern "C" void kernel_launch(void* const* d_in, const int* in_sizes, int n_in,
                              void* d_out, int out_size) {
    const float* X     = (const float*)d_in[0];
    const float* mask  = (const float*)d_in[1];
    const int*   ridx  = (const int*)  d_in[2];
    const int*   chl   = (const int*)  d_in[3];
    const float* Wpos  = (const float*)d_in[4];
    const float* bpos  = (const float*)d_in[5];
    const float* Wedge = (const float*)d_in[6];
    const float* gamma = (const float*)d_in[7];
    const float* beta  = (const float*)d_in[8];
    float* out = (float*)d_out;

    const int k2_smem = (Lv*3 + 4*Lv)*4 + 4*256*8;   // 65536 B
    cudaFuncSetAttribute(k2_topk, cudaFuncAttributeMaxDynamicSharedMemorySize, k2_smem);
    cudaFuncSetAttribute(k3_mma,  cudaFuncAttributeMaxDynamicSharedMemorySize, S_TOT);

    k0_prepW<<<(NKSG*16*2*32 + 255)/256, 256>>>(Wedge);
    k1_atoms<<<(Bv*Lv + 255)/256, 256>>>(X);
    k2_topk<<<Bv*Lv/4, 256, k2_smem>>>(mask);

    long long e_elems = (long long)Bv*Lv*Kv*CD;
    int write_idx = ((long long)out_size >= e_elems + (long long)Bv*Lv*Kv) ? 1 : 0;
    k3_mma<<<GRID3, 256, S_TOT>>>(ridx, chl, Wpos, bpos, gamma, beta, out, write_idx);
}

// round 10
// speedup vs baseline: 5.3142x; 1.1554x over previous
#include <cuda_runtime.h>
#include <cuda_fp16.h>
#include <cstdint>
#include <math.h>

#define Bv 4
#define Lv 2048
#define Kv 32
#define CD 128
#define NCH 7           // K chunks of 64
#define NKSG 28         // total k-steps of 16 (26 real)
#define GRID3 (Bv*Lv/4) // 2048 CTAs, 4 residues (128 edges) each

// Scratch (__device__ globals; no allocation allowed)
__device__ float g_atoms[Bv*Lv*5*3];
__device__ float g_ca[Bv*Lv*3];
__device__ int   g_eidx[Bv*Lv*Kv];
__device__ float g_dn[Bv*Lv*Kv];
// W in mma b-fragment layout: [ksg(28)][nt(16)][lane(32)] -> uint2 {b0,b1}, single fp16
__device__ uint2 g_Wf[NKSG*16*32];

__constant__ int c_PA[24] = {0,2,3,4,1,1,1,1,0,0,0,4,4,3,0,2,3,4,2,3,4,2,3,2};
__constant__ int c_PB[24] = {0,2,3,4,0,2,3,4,2,3,4,2,3,2,1,1,1,1,0,0,0,4,4,3};

__device__ __forceinline__ unsigned smem_u32(const void* p) {
    unsigned a;
    asm("{ .reg .u64 t; cvta.to.shared.u64 t, %1; cvt.u32.u64 %0, t; }" : "=r"(a) : "l"(p));
    return a;
}
__device__ __forceinline__ void ldsm4(unsigned* r, unsigned addr) {
    asm volatile("ldmatrix.sync.aligned.m8n8.x4.shared.b16 {%0,%1,%2,%3}, [%4];"
        : "=r"(r[0]), "=r"(r[1]), "=r"(r[2]), "=r"(r[3]) : "r"(addr));
}
__device__ __forceinline__ void mma16816(float* c, const unsigned* a, unsigned b0, unsigned b1) {
    asm volatile("mma.sync.aligned.m16n8k16.row.col.f32.f16.f16.f32 "
        "{%0,%1,%2,%3},{%4,%5,%6,%7},{%8,%9},{%0,%1,%2,%3};"
        : "+f"(c[0]), "+f"(c[1]), "+f"(c[2]), "+f"(c[3])
        : "r"(a[0]), "r"(a[1]), "r"(a[2]), "r"(a[3]), "r"(b0), "r"(b1));
}
__device__ __forceinline__ unsigned long long umin64(unsigned long long a, unsigned long long b) {
    return a < b ? a : b;
}

// ---------------------------------------------------------------------------
// k0: W_edge (416x128 f32) -> single fp16 fragments in mma b-frag layout.
// ---------------------------------------------------------------------------
__global__ void k0_prepW(const float* __restrict__ W) {
    int idx = blockIdx.x * 256 + threadIdx.x;     // NKSG*16*32 = 14336
    if (idx >= NKSG*16*32) return;
    int lane = idx & 31;
    int nt   = (idx >> 5) & 15;
    int ksg  = idx >> 9;
    int n  = nt*8 + (lane >> 2);
    int k0 = ksg*16 + (lane & 3)*2;
    unsigned r[2];
    #pragma unroll
    for (int h = 0; h < 2; h++) {
        int f0 = k0 + h*8;
        float v0 = (f0   < 416) ? W[f0 * CD + n]     : 0.0f;
        float v1 = (f0+1 < 416) ? W[(f0+1) * CD + n] : 0.0f;
        __half2 p = __floats2half2_rn(v0, v1);
        r[h] = *(unsigned*)&p;
    }
    g_Wf[idx] = make_uint2(r[0], r[1]);
}

// ---------------------------------------------------------------------------
// k1: atom table (N, Ca, C, O, Cb)
// ---------------------------------------------------------------------------
__global__ void k1_atoms(const float* __restrict__ X) {
    int i = blockIdx.x * blockDim.x + threadIdx.x;
    if (i >= Bv*Lv) return;
    const float* x = X + (size_t)i * 12;
    float Nx=x[0],Ny=x[1],Nz=x[2];
    float Ax=x[3],Ay=x[4],Az=x[5];
    float Cx=x[6],Cy=x[7],Cz=x[8];
    float Ox=x[9],Oy=x[10],Oz=x[11];
    float bx=Ax-Nx, by=Ay-Ny, bz=Az-Nz;
    float cx=Cx-Ax, cy=Cy-Ay, cz=Cz-Az;
    float ax=by*cz-bz*cy, ay=bz*cx-bx*cz, az=bx*cy-by*cx;
    float Cbx = -0.58273431f*ax + 0.56802827f*bx - 0.54067466f*cx + Ax;
    float Cby = -0.58273431f*ay + 0.56802827f*by - 0.54067466f*cy + Ay;
    float Cbz = -0.58273431f*az + 0.56802827f*bz - 0.54067466f*cz + Az;
    float* p = g_atoms + (size_t)i * 15;
    p[0]=Nx; p[1]=Ny; p[2]=Nz;
    p[3]=Ax; p[4]=Ay; p[5]=Az;
    p[6]=Cx; p[7]=Cy; p[8]=Cz;
    p[9]=Ox; p[10]=Oy; p[11]=Oz;
    p[12]=Cbx; p[13]=Cby; p[14]=Cbz;
    g_ca[i*3+0]=Ax; g_ca[i*3+1]=Ay; g_ca[i*3+2]=Az;
}

// ---------------------------------------------------------------------------
// k2: top-K, 4 rows per 256-thread CTA (proven R6 version).
// ---------------------------------------------------------------------------
__global__ void __launch_bounds__(256)
k2_topk(const float* __restrict__ mask) {
    extern __shared__ char smem_raw[];
    float* ca_s = (float*)smem_raw;
    float* d_s  = ca_s + Lv*3;
    unsigned long long* tmin = (unsigned long long*)(d_s + 4*Lv);
    __shared__ int s_maxi[4];

    int tid  = threadIdx.x;
    int wid  = tid >> 5, lane = tid & 31;
    int row0 = blockIdx.x * 4;
    int b    = row0 >> 11;

    if (tid < 4) s_maxi[tid] = 0;
    const float* cab = g_ca + (size_t)b * Lv * 3;
    for (int i = tid; i < Lv*3; i += 256) ca_s[i] = cab[i];
    __syncthreads();

    float cx[4], cy[4], cz[4], mi[4];
    #pragma unroll
    for (int r = 0; r < 4; r++) {
        int li = (row0 + r) & (Lv-1);
        cx[r] = ca_s[li*3+0]; cy[r] = ca_s[li*3+1]; cz[r] = ca_s[li*3+2];
        mi[r] = mask[(size_t)row0 + r];
    }
    const float* mb = mask + (size_t)b * Lv;

    int j0 = tid * 8;
    float Dreg[4][8], mbj[8];
    float lmax[4] = {0.f, 0.f, 0.f, 0.f};
    #pragma unroll
    for (int s = 0; s < 8; s++) {
        int j = j0 + s;
        float px = ca_s[j*3+0], py = ca_s[j*3+1], pz = ca_s[j*3+2];
        mbj[s] = mb[j];
        #pragma unroll
        for (int r = 0; r < 4; r++) {
            float dx = cx[r]-px, dy = cy[r]-py, dz = cz[r]-pz;
            float d  = sqrtf(dx*dx + dy*dy + dz*dz + 1e-6f);
            float D  = mi[r] * mbj[s] * d;
            Dreg[r][s] = D;
            lmax[r] = fmaxf(lmax[r], D);
        }
    }
    #pragma unroll
    for (int r = 0; r < 4; r++) {
        float v = lmax[r];
        #pragma unroll
        for (int o = 16; o; o >>= 1) v = fmaxf(v, __shfl_xor_sync(0xffffffffu, v, o));
        if (lane == 0) atomicMax(&s_maxi[r], __float_as_int(v));
    }
    __syncthreads();

    #pragma unroll
    for (int r = 0; r < 4; r++) {
        float Dmax = __int_as_float(s_maxi[r]);
        unsigned long long mn = ~0ULL;
        #pragma unroll
        for (int s = 0; s < 8; s++) {
            int j = j0 + s;
            float m2 = mi[r] * mbj[s];
            float Dadj = Dreg[r][s] + (1.0f - m2) * Dmax;
            d_s[r*Lv + j] = Dadj;
            unsigned long long k = (((unsigned long long)__float_as_uint(Dadj)) << 32) | (unsigned)j;
            mn = umin64(mn, k);
        }
        tmin[r*256 + tid] = mn;
    }
    __syncthreads();

    if (wid < 4) {
        int r = wid;
        int row = row0 + r;
        float* dr = d_s + r*Lv;
        unsigned long long m[8];
        #pragma unroll
        for (int s = 0; s < 8; s++) m[s] = tmin[r*256 + lane*8 + s];

        for (int rnd = 0; rnd < Kv; rnd++) {
            unsigned long long w = m[0];
            #pragma unroll
            for (int s = 1; s < 8; s++) w = umin64(w, m[s]);
            #pragma unroll
            for (int o = 16; o; o >>= 1) {
                unsigned long long v = __shfl_xor_sync(0xffffffffu, w, o);
                w = umin64(w, v);
            }
            int j = (int)(unsigned)(w & 0xffffffffu);
            if (lane == 0) {
                g_eidx[(size_t)row*Kv + rnd] = j;
                g_dn[(size_t)row*Kv + rnd]   = __uint_as_float((unsigned)(w >> 32));
            }
            int t = j >> 3;
            if ((t >> 3) == lane) {
                dr[j] = __int_as_float(0x7f800000);
                unsigned long long nm = ~0ULL;
                #pragma unroll
                for (int s = 0; s < 8; s++) {
                    int jj = t*8 + s;
                    float Dv = dr[jj];
                    unsigned long long k = (((unsigned long long)__float_as_uint(Dv)) << 32) | (unsigned)jj;
                    nm = umin64(nm, k);
                }
                m[t & 7] = nm;
            }
        }
    }
}

// ---------------------------------------------------------------------------
// k3: fused feature-build + single-pass fp16 mma GEMM + LayerNorm.
// CTA = 128 edges. Warp w owns n-cols [16w,16w+16) for all 128 rows;
// B fragments straight from g_Wf (L2-hot). RBF via direct __expf (proven).
// ---------------------------------------------------------------------------
#define S_A   0                           // 128*144 = 18432
#define S_NBA 18432                       // 128*15 f32 = 7680
#define S_QA  (S_NBA + 7680)              // 60 f32 -> 240
#define S_JV  (S_QA + 240)                // 128 int
#define S_DN  (S_JV + 512)                // 128 f32
#define S_DP  (S_DN + 512)                // 128 int
#define S_S1  (S_DP + 512)                // 128 f32 LN sum
#define S_S2  (S_S1 + 512)                // 128 f32 LN sumsq
#define S_TOT (S_S2 + 512)                // 28912 B

__global__ void __launch_bounds__(256)
k3_mma(const int* __restrict__ ridx, const int* __restrict__ chl,
       const float* __restrict__ Wpos, const float* __restrict__ bpos,
       const float* __restrict__ gamma, const float* __restrict__ beta,
       float* __restrict__ out, int write_idx) {
    extern __shared__ unsigned char sm[];
    unsigned sb = smem_u32(sm);
    int tid  = threadIdx.x;
    int wid  = tid >> 5, lane = tid & 31;
    int row0 = blockIdx.x * 4;
    int b    = row0 >> 11;

    float* nbA  = (float*)(sm + S_NBA);
    float* qa   = (float*)(sm + S_QA);
    int*   jv   = (int*)  (sm + S_JV);
    float* Dn   = (float*)(sm + S_DN);
    int*   dpos = (int*)  (sm + S_DP);
    float* s_s1 = (float*)(sm + S_S1);
    float* s_s2 = (float*)(sm + S_S2);

    if (tid < 128) {
        int r = tid >> 5;
        int brow = row0 + r;
        int j = g_eidx[(size_t)row0*Kv + tid];
        jv[tid] = j;
        Dn[tid] = g_dn[(size_t)row0*Kv + tid];
        int off = ridx[brow] - ridx[(size_t)b*Lv + j];
        int ech = (chl[brow] == chl[(size_t)b*Lv + j]) ? 1 : 0;
        int d = off + 32;
        d = d < 0 ? 0 : (d > 64 ? 64 : d);
        dpos[tid] = ech ? d : 65;
        s_s1[tid] = 0.0f;
        s_s2[tid] = 0.0f;
    }
    if (tid >= 160 && tid < 220) {
        int t = tid - 160;
        qa[t] = g_atoms[(size_t)(row0 + t/15)*15 + (t%15)];
    }
    __syncthreads();

    for (int t = tid; t < 128*15; t += 256) {
        nbA[t] = g_atoms[((size_t)b*Lv + jv[t/15])*15 + (t%15)];
    }
    __syncthreads();

    int e  = tid & 127;
    int s0 = tid >> 7;
    int r  = e >> 5;

    float acc[8][2][4];
    #pragma unroll
    for (int mt = 0; mt < 8; mt++)
        #pragma unroll
        for (int n2 = 0; n2 < 2; n2++) {
            acc[mt][n2][0]=0.f; acc[mt][n2][1]=0.f; acc[mt][n2][2]=0.f; acc[mt][n2][3]=0.f;
        }

    int arow  = lane & 15;
    int acol8 = (lane >> 4) * 8;
    const uint2* __restrict__ Wf = g_Wf;

    for (int kc = 0; kc < NCH; kc++) {
        // A chunk build
        #pragma unroll
        for (int pp = 0; pp < 2; pp++) {
            int ss = s0 + pp*2;
            int S  = kc*4 + ss;
            if (S < 26) {
                float vals[16];
                if (S == 0) {
                    const float4* wp = (const float4*)(Wpos + dpos[e]*16);
                    const float4* bb = (const float4*)bpos;
                    #pragma unroll
                    for (int q = 0; q < 4; q++) {
                        float4 a = wp[q], c = bb[q];
                        vals[q*4+0]=a.x+c.x; vals[q*4+1]=a.y+c.y; vals[q*4+2]=a.z+c.z; vals[q*4+3]=a.w+c.w;
                    }
                } else {
                    float D;
                    if (S == 1) D = Dn[e];
                    else {
                        int p = S - 2;
                        const float* A  = qa  + r*15 + c_PA[p]*3;
                        const float* Bp = nbA + e*15 + c_PB[p]*3;
                        float dx=A[0]-Bp[0], dy=A[1]-Bp[1], dz=A[2]-Bp[2];
                        D = sqrtf(dx*dx + dy*dy + dz*dz + 1e-6f);
                    }
                    #pragma unroll
                    for (int m = 0; m < 16; m++) {
                        float mu = 2.0f + (float)m * (4.0f/3.0f);
                        float z = (D - mu) * 0.8f;
                        vals[m] = __expf(-(z*z));
                    }
                }
                unsigned byteoff = (unsigned)e*144 + (unsigned)ss*32;
                #pragma unroll
                for (int q = 0; q < 2; q++) {
                    unsigned hp[4];
                    #pragma unroll
                    for (int j4 = 0; j4 < 4; j4++) {
                        __half2 h2 = __floats2half2_rn(vals[q*8 + j4*2], vals[q*8 + j4*2 + 1]);
                        hp[j4] = *(unsigned*)&h2;
                    }
                    *(uint4*)(sm + S_A + byteoff + q*16) = make_uint4(hp[0],hp[1],hp[2],hp[3]);
                }
            }
        }
        __syncthreads();

        int nks = (kc == NCH-1) ? 2 : 4;
        for (int ks = 0; ks < nks; ks++) {
            int ksg = kc*4 + ks;
            int k0  = ks * 16;
            uint2 bf[2];
            #pragma unroll
            for (int n2 = 0; n2 < 2; n2++)
                bf[n2] = Wf[((ksg*16) + (wid*2 + n2))*32 + lane];
            #pragma unroll
            for (int half = 0; half < 2; half++) {
                unsigned a[4][4];
                #pragma unroll
                for (int q = 0; q < 4; q++) {
                    int mt = half*4 + q;
                    ldsm4(a[q], sb + S_A + (unsigned)(mt*16 + arow)*144 + (unsigned)(k0 + acol8)*2);
                }
                #pragma unroll
                for (int q = 0; q < 4; q++) {
                    int mt = half*4 + q;
                    #pragma unroll
                    for (int n2 = 0; n2 < 2; n2++)
                        mma16816(acc[mt][n2], a[q], bf[n2].x, bf[n2].y);
                }
            }
        }
        __syncthreads();
    }

    if (write_idx && tid < 128) {
        out[(size_t)Bv*Lv*Kv*CD + (size_t)row0*Kv + tid] = (float)jv[tid];
    }

    // LayerNorm partials
    #pragma unroll
    for (int mt = 0; mt < 8; mt++) {
        float pA1 = acc[mt][0][0] + acc[mt][0][1] + acc[mt][1][0] + acc[mt][1][1];
        float pA2 = acc[mt][0][0]*acc[mt][0][0] + acc[mt][0][1]*acc[mt][0][1]
                  + acc[mt][1][0]*acc[mt][1][0] + acc[mt][1][1]*acc[mt][1][1];
        float pB1 = acc[mt][0][2] + acc[mt][0][3] + acc[mt][1][2] + acc[mt][1][3];
        float pB2 = acc[mt][0][2]*acc[mt][0][2] + acc[mt][0][3]*acc[mt][0][3]
                  + acc[mt][1][2]*acc[mt][1][2] + acc[mt][1][3]*acc[mt][1][3];
        #pragma unroll
        for (int o = 1; o <= 2; o <<= 1) {
            pA1 += __shfl_xor_sync(0xffffffffu, pA1, o);
            pA2 += __shfl_xor_sync(0xffffffffu, pA2, o);
            pB1 += __shfl_xor_sync(0xffffffffu, pB1, o);
            pB2 += __shfl_xor_sync(0xffffffffu, pB2, o);
        }
        if ((lane & 3) == 0) {
            int rA = mt*16 + (lane >> 2);
            atomicAdd(&s_s1[rA],     pA1);
            atomicAdd(&s_s2[rA],     pA2);
            atomicAdd(&s_s1[rA + 8], pB1);
            atomicAdd(&s_s2[rA + 8], pB2);
        }
    }
    __syncthreads();

    // normalize + write
    {
        int cb = wid*16 + 2*(lane & 3);
        float g0a = gamma[cb],     g1a = gamma[cb+1];
        float b0a = beta[cb],      b1a = beta[cb+1];
        float g0b = gamma[cb+8],   g1b = gamma[cb+9];
        float b0b = beta[cb+8],    b1b = beta[cb+9];
        #pragma unroll
        for (int mt = 0; mt < 8; mt++) {
            int rA = mt*16 + (lane >> 2);
            int rB = rA + 8;
            float muA = s_s1[rA] * (1.0f/128.0f);
            float vrA = s_s2[rA] * (1.0f/128.0f) - muA*muA;
            float ivA = 1.0f / sqrtf(vrA + 1e-5f);
            float muB = s_s1[rB] * (1.0f/128.0f);
            float vrB = s_s2[rB] * (1.0f/128.0f) - muB*muB;
            float ivB = 1.0f / sqrtf(vrB + 1e-5f);
            float* opA = out + ((size_t)row0*Kv + rA) * CD;
            float* opB = out + ((size_t)row0*Kv + rB) * CD;
            float2 oA0, oA1, oB0, oB1;
            oA0.x = (acc[mt][0][0] - muA)*ivA*g0a + b0a;
            oA0.y = (acc[mt][0][1] - muA)*ivA*g1a + b1a;
            oA1.x = (acc[mt][1][0] - muA)*ivA*g0b + b0b;
            oA1.y = (acc[mt][1][1] - muA)*ivA*g1b + b1b;
            oB0.x = (acc[mt][0][2] - muB)*ivB*g0a + b0a;
            oB0.y = (acc[mt][0][3] - muB)*ivB*g1a + b1a;
            oB1.x = (acc[mt][1][2] - muB)*ivB*g0b + b0b;
            oB1.y = (acc[mt][1][3] - muB)*ivB*g1b + b1b;
            *(float2*)(opA + cb)     = oA0;
            *(float2*)(opA + cb + 8) = oA1;
            *(float2*)(opB + cb)     = oB0;
            *(float2*)(opB + cb + 8) = oB1;
        }
    }
}

// ---------------------------------------------------------------------------
// Launch
// ---------------------------------------------------------------------------
extern "C" void kernel_launch(void* const* d_in, const int* in_sizes, int n_in,
                              void* d_out, int out_size) {
    const float* X     = (const float*)d_in[0];
    const float* mask  = (const float*)d_in[1];
    const int*   ridx  = (const int*)  d_in[2];
    const int*   chl   = (const int*)  d_in[3];
    const float* Wpos  = (const float*)d_in[4];
    const float* bpos  = (const float*)d_in[5];
    const float* Wedge = (const float*)d_in[6];
    const float* gamma = (const float*)d_in[7];
    const float* beta  = (const float*)d_in[8];
    float* out = (float*)d_out;

    const int k2_smem = (Lv*3 + 4*Lv)*4 + 4*256*8;   // 65536 B
    cudaFuncSetAttribute(k2_topk, cudaFuncAttributeMaxDynamicSharedMemorySize, k2_smem);
    cudaFuncSetAttribute(k3_mma,  cudaFuncAttributeMaxDynamicSharedMemorySize, S_TOT);

    k0_prepW<<<(NKSG*16*32 + 255)/256, 256>>>(Wedge);
    k1_atoms<<<(Bv*Lv + 255)/256, 256>>>(X);
    k2_topk<<<Bv*Lv/4, 256, k2_smem>>>(mask);

    long long e_elems = (long long)Bv*Lv*Kv*CD;
    int write_idx = ((long long)out_size >= e_elems + (long long)Bv*Lv*Kv) ? 1 : 0;
    k3_mma<<<GRID3, 256, S_TOT>>>(ridx, chl, Wpos, bpos, gamma, beta, out, write_idx);
}